// round 2
// baseline (speedup 1.0000x reference)
#include <cuda_runtime.h>
#include <cstdint>

#define KCAP 512
#define DDIM 1024
#define BMAX 16384

// ---------------- device scratch (no allocations allowed) ----------------
__device__ __align__(16) float g_Mt[KCAP * KCAP];   // Mt[k][j] = (k==j) + 0.1*A_diff[j][k]
__device__ float g_nsp[4 * BMAX];                   // partial norm_sq per column-group
__device__ float g_agr[BMAX];                       // agreement per row
__device__ __align__(16) float g_u1[KCAP];
__device__ __align__(16) float g_w1[KCAP];
__device__ float g_sc[2];                           // {1/T_eff, c}

// ---------------- block reductions (256 threads) ----------------
__device__ __forceinline__ float blkMax256(float v, float* sc) {
    #pragma unroll
    for (int o = 16; o > 0; o >>= 1) v = fmaxf(v, __shfl_xor_sync(0xffffffffu, v, o));
    if ((threadIdx.x & 31) == 0) sc[threadIdx.x >> 5] = v;
    __syncthreads();
    float r = sc[0];
    #pragma unroll
    for (int i = 1; i < 8; i++) r = fmaxf(r, sc[i]);
    __syncthreads();
    return r;
}

__device__ __forceinline__ float blkSum256(float v, float* sc) {
    #pragma unroll
    for (int o = 16; o > 0; o >>= 1) v += __shfl_xor_sync(0xffffffffu, v, o);
    if ((threadIdx.x & 31) == 0) sc[threadIdx.x >> 5] = v;
    __syncthreads();
    float r = sc[0];
    #pragma unroll
    for (int i = 1; i < 8; i++) r += sc[i];
    __syncthreads();
    return r;
}

// ---------------- P0: scalars ----------------
__global__ void k_scalars(const float* __restrict__ lT, const float* __restrict__ lc,
                          const void* __restrict__ tp) {
    if (threadIdx.x == 0) {
        unsigned w = *(const unsigned*)tp;
        float ft = __uint_as_float(w);
        float tempv = (fabsf(ft) > 1e-30f && fabsf(ft) < 1e30f) ? ft : (float)(int)w;
        float T = fminf(fmaxf(expf(lT[0]) * tempv, 0.05f), 10.0f);
        g_sc[0] = 1.0f / T;
        g_sc[1] = fminf(fmaxf(expf(lc[0]), 0.01f), 10.0f);
    }
}

// ---------------- P1: symmetric softmax -> Mt (transposed, identity folded) ----------------
__global__ void __launch_bounds__(256) k_adiff(const float* __restrict__ A) {
    __shared__ float scr[8];
    const int j = blockIdx.x, tid = threadIdx.x;
    float v0 = 0.5f * (A[j * KCAP + tid]       + A[tid * KCAP + j]);
    float v1 = 0.5f * (A[j * KCAP + tid + 256] + A[(tid + 256) * KCAP + j]);
    float M = blkMax256(fmaxf(v0, v1), scr);
    float e0 = __expf(v0 - M), e1 = __expf(v1 - M);
    float S = blkSum256(e0 + e1, scr);
    float r = 0.1f / S;
    g_Mt[tid * KCAP + j]         = fmaf(e0, r, (tid == j)         ? 1.0f : 0.0f);
    g_Mt[(tid + 256) * KCAP + j] = fmaf(e1, r, ((tid + 256) == j) ? 1.0f : 0.0f);
}

// ---------------- P2: fold iteration 0: u1 = b_run@M.T, w1 = softmax(b_run/T)@M.T ----------------
__global__ void __launch_bounds__(256) k_prep(const float* __restrict__ brun) {
    __shared__ float br[KCAP];
    __shared__ float sg[KCAP];
    __shared__ float scr[8];
    const int tid = threadIdx.x;
    const float invT = g_sc[0];
    float v0 = brun[tid], v1 = brun[tid + 256];
    br[tid] = v0; br[tid + 256] = v1;
    float M = blkMax256(fmaxf(v0, v1), scr);
    float e0 = __expf((v0 - M) * invT), e1 = __expf((v1 - M) * invT);
    float S = blkSum256(e0 + e1, scr);
    float is = 1.0f / S;
    sg[tid] = e0 * is; sg[tid + 256] = e1 * is;
    __syncthreads();
    const int j = blockIdx.x * 256 + tid;
    float u = 0.0f, w = 0.0f;
    #pragma unroll 8
    for (int k = 0; k < KCAP; k++) {
        float mt = g_Mt[k * KCAP + j];
        u = fmaf(br[k], mt, u);
        w = fmaf(sg[k], mt, w);
    }
    g_u1[j] = u; g_w1[j] = w;
}

// ---------------- P3: fused x@W.T + per-row sum-of-squares (partials) ----------------
// grid (B/128, 4), 256 threads. Block: 128 rows x 128 caps, K=1024 in tiles of 8.
__global__ void __launch_bounds__(256) k_norm(const float* __restrict__ x,
                                              const float* __restrict__ W, int B) {
    __shared__ float x_s[8 * 128];
    __shared__ float w_s[8 * 128];
    __shared__ float red2[128 * 16];
    const int tid = threadIdx.x;
    const int row0 = blockIdx.x * 128;
    const int col0 = blockIdx.y * 128;
    const int rg = tid >> 4, cg = tid & 15;
    const int rr = tid >> 1, h = tid & 1;

    float acc[8][8];
    #pragma unroll
    for (int i = 0; i < 8; i++)
        #pragma unroll
        for (int j = 0; j < 8; j++) acc[i][j] = 0.0f;

    const float* xp = x + (size_t)(row0 + rr) * DDIM + h * 4;
    const float* wp = W + (size_t)(col0 + rr) * DDIM + h * 4;

    for (int kt = 0; kt < DDIM / 8; kt++) {
        __syncthreads();
        float4 xv = *(const float4*)(xp + kt * 8);
        float4 wv = *(const float4*)(wp + kt * 8);
        x_s[(h * 4 + 0) * 128 + rr] = xv.x;
        x_s[(h * 4 + 1) * 128 + rr] = xv.y;
        x_s[(h * 4 + 2) * 128 + rr] = xv.z;
        x_s[(h * 4 + 3) * 128 + rr] = xv.w;
        w_s[(h * 4 + 0) * 128 + rr] = wv.x;
        w_s[(h * 4 + 1) * 128 + rr] = wv.y;
        w_s[(h * 4 + 2) * 128 + rr] = wv.z;
        w_s[(h * 4 + 3) * 128 + rr] = wv.w;
        __syncthreads();
        #pragma unroll
        for (int k = 0; k < 8; k++) {
            float4 xa = *(const float4*)&x_s[k * 128 + rg * 8];
            float4 xb = *(const float4*)&x_s[k * 128 + rg * 8 + 4];
            float4 wa = *(const float4*)&w_s[k * 128 + cg * 8];
            float4 wb = *(const float4*)&w_s[k * 128 + cg * 8 + 4];
            float xf[8] = {xa.x, xa.y, xa.z, xa.w, xb.x, xb.y, xb.z, xb.w};
            float wf[8] = {wa.x, wa.y, wa.z, wa.w, wb.x, wb.y, wb.z, wb.w};
            #pragma unroll
            for (int i = 0; i < 8; i++)
                #pragma unroll
                for (int j = 0; j < 8; j++)
                    acc[i][j] = fmaf(xf[i], wf[j], acc[i][j]);
        }
    }
    // square-accumulate each output element, reduce within thread over cols
    float rs[8];
    #pragma unroll
    for (int i = 0; i < 8; i++) {
        float s = 0.0f;
        #pragma unroll
        for (int j = 0; j < 8; j++) s = fmaf(acc[i][j], acc[i][j], s);
        rs[i] = s;
    }
    __syncthreads();
    #pragma unroll
    for (int i = 0; i < 8; i++) red2[(rg * 8 + i) * 16 + cg] = rs[i];
    __syncthreads();
    if (tid < 128) {
        float s = 0.0f;
        #pragma unroll
        for (int c = 0; c < 16; c++) s += red2[tid * 16 + c];
        g_nsp[(size_t)blockIdx.y * B + row0 + tid] = s;   // deterministic
    }
}

// ---------------- P4: agreement ----------------
__global__ void k_agree(int B) {
    int i = blockIdx.x * 256 + threadIdx.x;
    if (i < B) {
        float c = g_sc[1];
        float ns = g_nsp[i] + g_nsp[B + i] + g_nsp[2 * B + i] + g_nsp[3 * B + i];
        ns = fmaxf(ns, 1e-10f);
        float sc2 = c * ns / (1.0f + c * ns);
        g_agr[i] = sc2 * sqrtf(ns);
    }
}

// ---------------- MAIN: 4 routing iterations + final softmax, SMEM-resident b ----------------
#define BPAD 516
#define SMEM_MAIN_BYTES ((32 * BPAD + 256 + 32) * 4)

__global__ void __launch_bounds__(256, 2) k_main(float* __restrict__ out) {
    extern __shared__ float sm[];
    float* b_s  = sm;                 // [32][516]
    float* red  = sm + 32 * BPAD;     // [256]
    float* agrs = red + 256;          // [32]

    const int tid = threadIdx.x;
    const int row0 = blockIdx.x * 32;
    const float invT = g_sc[0];

    if (tid < 32) agrs[tid] = g_agr[row0 + tid];
    float u0 = g_u1[tid],       w0 = g_w1[tid];
    float u1 = g_u1[tid + 256], w1 = g_w1[tid + 256];
    __syncthreads();
    #pragma unroll 4
    for (int r2 = 0; r2 < 32; r2++) {
        float a = agrs[r2];
        b_s[r2 * BPAD + tid]       = fmaf(a, w0, u0);
        b_s[r2 * BPAD + tid + 256] = fmaf(a, w1, u1);
    }
    __syncthreads();

    const int r = tid >> 3;           // row 0..31
    const int c0 = (tid & 7) * 64;    // 64-col segment
    const float a_r = agrs[r];
    float* brow = b_s + r * BPAD + c0;

    for (int it = 0; it < 4; it++) {
        // ---- b += a * softmax(b/T) ----
        float mx = -3.4e38f;
        #pragma unroll
        for (int kk = 0; kk < 64; kk += 4) {
            float4 v = *(const float4*)(brow + kk);
            mx = fmaxf(mx, fmaxf(fmaxf(v.x, v.y), fmaxf(v.z, v.w)));
        }
        red[tid] = mx; __syncthreads();
        float m = red[r * 8];
        #pragma unroll
        for (int q = 1; q < 8; q++) m = fmaxf(m, red[r * 8 + q]);
        __syncthreads();
        float s = 0.0f;
        #pragma unroll
        for (int kk = 0; kk < 64; kk += 4) {
            float4 v = *(const float4*)(brow + kk);
            s += __expf((v.x - m) * invT) + __expf((v.y - m) * invT)
               + __expf((v.z - m) * invT) + __expf((v.w - m) * invT);
        }
        red[tid] = s; __syncthreads();
        float S = red[r * 8];
        #pragma unroll
        for (int q = 1; q < 8; q++) S += red[r * 8 + q];
        float aS = a_r / S;
        #pragma unroll
        for (int kk = 0; kk < 64; kk += 4) {
            float4 v = *(const float4*)(brow + kk);
            v.x = fmaf(aS, __expf((v.x - m) * invT), v.x);
            v.y = fmaf(aS, __expf((v.y - m) * invT), v.y);
            v.z = fmaf(aS, __expf((v.z - m) * invT), v.z);
            v.w = fmaf(aS, __expf((v.w - m) * invT), v.w);
            *(float4*)(brow + kk) = v;
        }
        __syncthreads();

        // ---- b = b @ M.T  (acc over k, Mt L2-resident) ----
        float acc0[32], acc1[32];
        #pragma unroll
        for (int r2 = 0; r2 < 32; r2++) { acc0[r2] = 0.0f; acc1[r2] = 0.0f; }
        const float* mt0 = g_Mt + tid;
        const float* mt1 = g_Mt + tid + 256;
        #pragma unroll 1
        for (int k = 0; k < KCAP; k += 4) {
            float m00 = mt0[(k + 0) * KCAP], m10 = mt1[(k + 0) * KCAP];
            float m01 = mt0[(k + 1) * KCAP], m11 = mt1[(k + 1) * KCAP];
            float m02 = mt0[(k + 2) * KCAP], m12 = mt1[(k + 2) * KCAP];
            float m03 = mt0[(k + 3) * KCAP], m13 = mt1[(k + 3) * KCAP];
            #pragma unroll
            for (int r2 = 0; r2 < 32; r2++) {
                float4 bv = *(const float4*)&b_s[r2 * BPAD + k];
                float a0 = acc0[r2], a1 = acc1[r2];
                a0 = fmaf(bv.x, m00, a0); a1 = fmaf(bv.x, m10, a1);
                a0 = fmaf(bv.y, m01, a0); a1 = fmaf(bv.y, m11, a1);
                a0 = fmaf(bv.z, m02, a0); a1 = fmaf(bv.z, m12, a1);
                a0 = fmaf(bv.w, m03, a0); a1 = fmaf(bv.w, m13, a1);
                acc0[r2] = a0; acc1[r2] = a1;
            }
        }
        __syncthreads();
        #pragma unroll
        for (int r2 = 0; r2 < 32; r2++) {
            b_s[r2 * BPAD + tid]       = acc0[r2];
            b_s[r2 * BPAD + tid + 256] = acc1[r2];
        }
        __syncthreads();
    }

    // ---- theta = softmax(b/T) -> out ----
    {
        float mx = -3.4e38f;
        #pragma unroll
        for (int kk = 0; kk < 64; kk += 4) {
            float4 v = *(const float4*)(brow + kk);
            mx = fmaxf(mx, fmaxf(fmaxf(v.x, v.y), fmaxf(v.z, v.w)));
        }
        red[tid] = mx; __syncthreads();
        float m = red[r * 8];
        #pragma unroll
        for (int q = 1; q < 8; q++) m = fmaxf(m, red[r * 8 + q]);
        __syncthreads();
        float s = 0.0f;
        #pragma unroll
        for (int kk = 0; kk < 64; kk += 4) {
            float4 v = *(const float4*)(brow + kk);
            s += __expf((v.x - m) * invT) + __expf((v.y - m) * invT)
               + __expf((v.z - m) * invT) + __expf((v.w - m) * invT);
        }
        red[tid] = s; __syncthreads();
        float S = red[r * 8];
        #pragma unroll
        for (int q = 1; q < 8; q++) S += red[r * 8 + q];
        float iS = 1.0f / S;
        float* op = out + (size_t)(row0 + r) * KCAP + c0;
        #pragma unroll
        for (int kk = 0; kk < 64; kk += 4) {
            float4 v = *(const float4*)(brow + kk);
            float4 o;
            o.x = __expf((v.x - m) * invT) * iS;
            o.y = __expf((v.y - m) * invT) * iS;
            o.z = __expf((v.z - m) * invT) * iS;
            o.w = __expf((v.w - m) * invT) * iS;
            *(float4*)(op + kk) = o;
        }
    }
}

// ---------------- launcher ----------------
extern "C" void kernel_launch(void* const* d_in, const int* in_sizes, int n_in,
                              void* d_out, int out_size) {
    const float* x    = (const float*)d_in[0];
    const float* W    = (const float*)d_in[1];
    const float* A    = (const float*)d_in[2];
    const float* lT   = (const float*)d_in[3];
    const float* lc   = (const float*)d_in[4];
    const float* brun = (const float*)d_in[5];
    const void*  temp = d_in[6];
    const int B = in_sizes[0] / DDIM;   // 16384

    cudaFuncSetAttribute(k_main, cudaFuncAttributeMaxDynamicSharedMemorySize,
                         SMEM_MAIN_BYTES);

    k_scalars<<<1, 32>>>(lT, lc, temp);
    k_adiff<<<KCAP, 256>>>(A);
    k_prep<<<2, 256>>>(brun);
    k_norm<<<dim3(B / 128, 4), 256>>>(x, W, B);
    k_agree<<<(B + 255) / 256, 256>>>(B);
    k_main<<<B / 32, 256, SMEM_MAIN_BYTES>>>((float*)d_out);
}

// round 3
// speedup vs baseline: 1.5481x; 1.5481x over previous
#include <cuda_runtime.h>
#include <cstdint>

#define KCAP 512
#define DDIM 1024
#define BMAX 16384
#define PAD  520

// ---------------- device scratch (no allocations allowed) ----------------
__device__ __align__(16) float g_At[KCAP * KCAP];   // At[k*512+n] = tf32(0.1*A_diff[n][k])
__device__ float g_nsp[4 * BMAX];
__device__ float g_agr[BMAX];
__device__ __align__(16) float g_u1[KCAP];
__device__ __align__(16) float g_w1[KCAP];
__device__ float g_sc[2];                            // {1/T_eff, c}

// ---------------- helpers ----------------
__device__ __forceinline__ float blkMax256(float v, float* sc) {
    #pragma unroll
    for (int o = 16; o > 0; o >>= 1) v = fmaxf(v, __shfl_xor_sync(0xffffffffu, v, o));
    if ((threadIdx.x & 31) == 0) sc[threadIdx.x >> 5] = v;
    __syncthreads();
    float r = sc[0];
    #pragma unroll
    for (int i = 1; i < 8; i++) r = fmaxf(r, sc[i]);
    __syncthreads();
    return r;
}
__device__ __forceinline__ float blkSum256(float v, float* sc) {
    #pragma unroll
    for (int o = 16; o > 0; o >>= 1) v += __shfl_xor_sync(0xffffffffu, v, o);
    if ((threadIdx.x & 31) == 0) sc[threadIdx.x >> 5] = v;
    __syncthreads();
    float r = sc[0];
    #pragma unroll
    for (int i = 1; i < 8; i++) r += sc[i];
    __syncthreads();
    return r;
}
__device__ __forceinline__ uint32_t f2tf(float f) {
    uint32_t r;
    asm("cvt.rna.tf32.f32 %0, %1;" : "=r"(r) : "f"(f));
    return r;
}
__device__ __forceinline__ void cp16(float* dst, const float* src) {
    unsigned s = (unsigned)__cvta_generic_to_shared(dst);
    asm volatile("cp.async.cg.shared.global [%0], [%1], 16;\n" :: "r"(s), "l"(src));
}
__device__ __forceinline__ void cpcommit() { asm volatile("cp.async.commit_group;\n"); }
template <int N>
__device__ __forceinline__ void cpwait() { asm volatile("cp.async.wait_group %0;\n" :: "n"(N)); }

#define MMA_TF32(c, a0, a1, a2, a3, b0, b1)                                            \
    asm volatile(                                                                       \
        "mma.sync.aligned.m16n8k8.row.col.f32.tf32.tf32.f32 "                           \
        "{%0,%1,%2,%3},{%4,%5,%6,%7},{%8,%9},{%0,%1,%2,%3};"                            \
        : "+f"((c)[0]), "+f"((c)[1]), "+f"((c)[2]), "+f"((c)[3])                        \
        : "r"(a0), "r"(a1), "r"(a2), "r"(a3), "r"(b0), "r"(b1))

// ---------------- P0: scalars ----------------
__global__ void k_scalars(const float* __restrict__ lT, const float* __restrict__ lc,
                          const void* __restrict__ tp) {
    if (threadIdx.x == 0) {
        unsigned w = *(const unsigned*)tp;
        float ft = __uint_as_float(w);
        float tempv = (fabsf(ft) > 1e-30f && fabsf(ft) < 1e30f) ? ft : (float)(int)w;
        float T = fminf(fmaxf(expf(lT[0]) * tempv, 0.05f), 10.0f);
        g_sc[0] = 1.0f / T;
        g_sc[1] = fminf(fmaxf(expf(lc[0]), 0.01f), 10.0f);
    }
}

// ---------------- P1: symmetric softmax -> At (transposed, scaled 0.1, tf32-rounded) ----------------
__global__ void __launch_bounds__(256) k_adiff(const float* __restrict__ A) {
    __shared__ float scr[8];
    const int j = blockIdx.x, tid = threadIdx.x;
    float v0 = 0.5f * (A[j * KCAP + tid]       + A[tid * KCAP + j]);
    float v1 = 0.5f * (A[j * KCAP + tid + 256] + A[(tid + 256) * KCAP + j]);
    float M = blkMax256(fmaxf(v0, v1), scr);
    float e0 = __expf(v0 - M), e1 = __expf(v1 - M);
    float S = blkSum256(e0 + e1, scr);
    float r = 0.1f / S;
    g_At[tid * KCAP + j]         = __uint_as_float(f2tf(e0 * r));
    g_At[(tid + 256) * KCAP + j] = __uint_as_float(f2tf(e1 * r));
}

// ---------------- P2: fold iteration 0: u1 = b_run@M.T, w1 = softmax(b_run/T)@M.T ----------------
// M = I + 0.1*A_diff, so u1_j = br_j + sum_k br_k * At[k][j] (same for w1 with sigma0).
__global__ void __launch_bounds__(256) k_prep(const float* __restrict__ brun) {
    __shared__ float br[KCAP];
    __shared__ float sg[KCAP];
    __shared__ float scr[8];
    const int tid = threadIdx.x;
    const float invT = g_sc[0];
    float v0 = brun[tid], v1 = brun[tid + 256];
    br[tid] = v0; br[tid + 256] = v1;
    float M = blkMax256(fmaxf(v0, v1), scr);
    float e0 = __expf((v0 - M) * invT), e1 = __expf((v1 - M) * invT);
    float S = blkSum256(e0 + e1, scr);
    float is = 1.0f / S;
    sg[tid] = e0 * is; sg[tid + 256] = e1 * is;
    __syncthreads();
    const int j = blockIdx.x * 256 + tid;
    float u = 0.0f, w = 0.0f;
    #pragma unroll 8
    for (int k = 0; k < KCAP; k++) {
        float at = g_At[k * KCAP + j];
        u = fmaf(br[k], at, u);
        w = fmaf(sg[k], at, w);
    }
    g_u1[j] = br[j] + u;
    g_w1[j] = sg[j] + w;
}

// ---------------- P3: fused x@W.T + per-row sum-of-squares (fp32, unchanged) ----------------
__global__ void __launch_bounds__(256) k_norm(const float* __restrict__ x,
                                              const float* __restrict__ W, int B) {
    __shared__ float x_s[8 * 128];
    __shared__ float w_s[8 * 128];
    __shared__ float red2[128 * 16];
    const int tid = threadIdx.x;
    const int row0 = blockIdx.x * 128;
    const int col0 = blockIdx.y * 128;
    const int rg = tid >> 4, cg = tid & 15;
    const int rr = tid >> 1, h = tid & 1;

    float acc[8][8];
    #pragma unroll
    for (int i = 0; i < 8; i++)
        #pragma unroll
        for (int j = 0; j < 8; j++) acc[i][j] = 0.0f;

    const float* xp = x + (size_t)(row0 + rr) * DDIM + h * 4;
    const float* wp = W + (size_t)(col0 + rr) * DDIM + h * 4;

    for (int kt = 0; kt < DDIM / 8; kt++) {
        __syncthreads();
        float4 xv = *(const float4*)(xp + kt * 8);
        float4 wv = *(const float4*)(wp + kt * 8);
        x_s[(h * 4 + 0) * 128 + rr] = xv.x;
        x_s[(h * 4 + 1) * 128 + rr] = xv.y;
        x_s[(h * 4 + 2) * 128 + rr] = xv.z;
        x_s[(h * 4 + 3) * 128 + rr] = xv.w;
        w_s[(h * 4 + 0) * 128 + rr] = wv.x;
        w_s[(h * 4 + 1) * 128 + rr] = wv.y;
        w_s[(h * 4 + 2) * 128 + rr] = wv.z;
        w_s[(h * 4 + 3) * 128 + rr] = wv.w;
        __syncthreads();
        #pragma unroll
        for (int k = 0; k < 8; k++) {
            float4 xa = *(const float4*)&x_s[k * 128 + rg * 8];
            float4 xb = *(const float4*)&x_s[k * 128 + rg * 8 + 4];
            float4 wa = *(const float4*)&w_s[k * 128 + cg * 8];
            float4 wb = *(const float4*)&w_s[k * 128 + cg * 8 + 4];
            float xf[8] = {xa.x, xa.y, xa.z, xa.w, xb.x, xb.y, xb.z, xb.w};
            float wf[8] = {wa.x, wa.y, wa.z, wa.w, wb.x, wb.y, wb.z, wb.w};
            #pragma unroll
            for (int i = 0; i < 8; i++)
                #pragma unroll
                for (int j = 0; j < 8; j++)
                    acc[i][j] = fmaf(xf[i], wf[j], acc[i][j]);
        }
    }
    float rs[8];
    #pragma unroll
    for (int i = 0; i < 8; i++) {
        float s = 0.0f;
        #pragma unroll
        for (int j = 0; j < 8; j++) s = fmaf(acc[i][j], acc[i][j], s);
        rs[i] = s;
    }
    __syncthreads();
    #pragma unroll
    for (int i = 0; i < 8; i++) red2[(rg * 8 + i) * 16 + cg] = rs[i];
    __syncthreads();
    if (tid < 128) {
        float s = 0.0f;
        #pragma unroll
        for (int c = 0; c < 16; c++) s += red2[tid * 16 + c];
        g_nsp[(size_t)blockIdx.y * B + row0 + tid] = s;
    }
}

// ---------------- P4: agreement ----------------
__global__ void k_agree(int B) {
    int i = blockIdx.x * 256 + threadIdx.x;
    if (i < B) {
        float c = g_sc[1];
        float ns = g_nsp[i] + g_nsp[B + i] + g_nsp[2 * B + i] + g_nsp[3 * B + i];
        ns = fmaxf(ns, 1e-10f);
        float sc2 = c * ns / (1.0f + c * ns);
        g_agr[i] = sc2 * sqrtf(ns);
    }
}

// ---------------- MAIN: 4 routing iterations, tf32 tensor-core diffusion GEMM ----------------
// 64 rows/block, 512 threads (16 warps). b SMEM-resident.
// GEMM per iter: d = b @ At  (At = 0.1*A_diff^T, tf32), hi/lo split of b for fp32-grade accuracy.
#define SMEM_MAIN_FLOATS (64 * PAD + 2 * 8 * PAD + 512 + 64)
#define SMEM_MAIN_BYTES  (SMEM_MAIN_FLOATS * 4)

__global__ void __launch_bounds__(512, 1) k_main(float* __restrict__ out) {
    extern __shared__ float sm[];
    float* b_s  = sm;                       // [64][PAD]
    float* slab = sm + 64 * PAD;            // 2 x [8][PAD]
    float* red  = slab + 2 * 8 * PAD;       // [512]
    float* agrs = red + 512;                // [64]

    const int tid  = threadIdx.x;
    const int lane = tid & 31;
    const int wrp  = tid >> 5;              // 0..15
    const int rbase = (wrp & 3) * 16;       // row stripe
    const int nbase = (wrp >> 2) * 128;     // col stripe
    const int row0 = blockIdx.x * 64;
    const float invT = g_sc[0];

    // softmax thread mapping: 8 threads per row
    const int r  = tid >> 3;                // 0..63
    const int t8 = tid & 7;
    float* base = b_s + r * PAD + t8 * 4;

    // ---- init: b = u1 + a*w1 ----
    if (tid < 64) agrs[tid] = g_agr[row0 + tid];
    float uj = g_u1[tid];
    float wj = g_w1[tid];
    __syncthreads();
    #pragma unroll 8
    for (int r2 = 0; r2 < 64; r2++)
        b_s[r2 * PAD + tid] = fmaf(agrs[r2], wj, uj);
    __syncthreads();

    for (int it = 0; it < 4; it++) {
        // prefetch At chunk 0 (overlaps with softmax)
        {
            const float* src = g_At;
            float* dst = slab;
            #pragma unroll
            for (int q = 0; q < 2; q++) {
                int lin = tid + q * 512;
                int rowk = lin >> 7, c4 = (lin & 127) * 4;
                cp16(dst + rowk * PAD + c4, src + rowk * KCAP + c4);
            }
            cpcommit();
        }

        // ---- b += a * softmax(b/T) ----
        float mx = -3.4e38f;
        #pragma unroll
        for (int j = 0; j < 16; j++) {
            float4 v = *(const float4*)(base + j * 32);
            mx = fmaxf(mx, fmaxf(fmaxf(v.x, v.y), fmaxf(v.z, v.w)));
        }
        red[tid] = mx; __syncthreads();
        float m = red[r * 8];
        #pragma unroll
        for (int q = 1; q < 8; q++) m = fmaxf(m, red[r * 8 + q]);
        __syncthreads();
        float s = 0.0f;
        #pragma unroll
        for (int j = 0; j < 16; j++) {
            float4 v = *(const float4*)(base + j * 32);
            s += __expf((v.x - m) * invT) + __expf((v.y - m) * invT)
               + __expf((v.z - m) * invT) + __expf((v.w - m) * invT);
        }
        red[tid] = s; __syncthreads();
        float S = red[r * 8];
        #pragma unroll
        for (int q = 1; q < 8; q++) S += red[r * 8 + q];
        float aS = agrs[r] / S;
        #pragma unroll
        for (int j = 0; j < 16; j++) {
            float4 v = *(const float4*)(base + j * 32);
            v.x = fmaf(aS, __expf((v.x - m) * invT), v.x);
            v.y = fmaf(aS, __expf((v.y - m) * invT), v.y);
            v.z = fmaf(aS, __expf((v.z - m) * invT), v.z);
            v.w = fmaf(aS, __expf((v.w - m) * invT), v.w);
            *(float4*)(base + j * 32) = v;
        }
        __syncthreads();

        // ---- d = b @ At (tf32 mma, hi/lo split), acc in regs ----
        float acc[16][4];
        #pragma unroll
        for (int t = 0; t < 16; t++)
            #pragma unroll
            for (int q = 0; q < 4; q++) acc[t][q] = 0.0f;

        for (int kc = 0; kc < 64; kc++) {
            if (kc < 63) {
                const float* src = g_At + (kc + 1) * 8 * KCAP;
                float* dst = slab + ((kc + 1) & 1) * 8 * PAD;
                #pragma unroll
                for (int q = 0; q < 2; q++) {
                    int lin = tid + q * 512;
                    int rowk = lin >> 7, c4 = (lin & 127) * 4;
                    cp16(dst + rowk * PAD + c4, src + rowk * KCAP + c4);
                }
                cpcommit();
                cpwait<1>();
            } else {
                cpwait<0>();
            }
            __syncthreads();

            const float* sb = slab + (kc & 1) * 8 * PAD;
            const int k0 = kc * 8;

            // A fragments (16x8 tile of b rows)
            const float* ap = b_s + (rbase + (lane >> 2)) * PAD + k0 + (lane & 3);
            float v00 = ap[0];
            float v10 = ap[8 * PAD];
            float v01 = ap[4];
            float v11 = ap[8 * PAD + 4];
            uint32_t h0 = f2tf(v00), h1 = f2tf(v10), h2 = f2tf(v01), h3 = f2tf(v11);
            uint32_t l0 = f2tf(v00 - __uint_as_float(h0));
            uint32_t l1 = f2tf(v10 - __uint_as_float(h1));
            uint32_t l2 = f2tf(v01 - __uint_as_float(h2));
            uint32_t l3 = f2tf(v11 - __uint_as_float(h3));

            const float* bp0 = sb + (lane & 3) * PAD + nbase + (lane >> 2);
            const float* bp1 = bp0 + 4 * PAD;
            #pragma unroll
            for (int t = 0; t < 16; t++) {
                uint32_t b0 = __float_as_uint(bp0[t * 8]);
                uint32_t b1 = __float_as_uint(bp1[t * 8]);
                MMA_TF32(acc[t], h0, h1, h2, h3, b0, b1);
                MMA_TF32(acc[t], l0, l1, l2, l3, b0, b1);
            }
            __syncthreads();
        }

        // ---- b += d ----
        float* ep = b_s + (rbase + (lane >> 2)) * PAD + nbase + 2 * (lane & 3);
        #pragma unroll
        for (int t = 0; t < 16; t++) {
            float* p = ep + t * 8;
            p[0]           += acc[t][0];
            p[1]           += acc[t][1];
            p[8 * PAD]     += acc[t][2];
            p[8 * PAD + 1] += acc[t][3];
        }
        __syncthreads();
    }

    // ---- theta = softmax(b/T) -> out ----
    {
        float mx = -3.4e38f;
        #pragma unroll
        for (int j = 0; j < 16; j++) {
            float4 v = *(const float4*)(base + j * 32);
            mx = fmaxf(mx, fmaxf(fmaxf(v.x, v.y), fmaxf(v.z, v.w)));
        }
        red[tid] = mx; __syncthreads();
        float m = red[r * 8];
        #pragma unroll
        for (int q = 1; q < 8; q++) m = fmaxf(m, red[r * 8 + q]);
        __syncthreads();
        float s = 0.0f;
        #pragma unroll
        for (int j = 0; j < 16; j++) {
            float4 v = *(const float4*)(base + j * 32);
            s += __expf((v.x - m) * invT) + __expf((v.y - m) * invT)
               + __expf((v.z - m) * invT) + __expf((v.w - m) * invT);
        }
        red[tid] = s; __syncthreads();
        float S = red[r * 8];
        #pragma unroll
        for (int q = 1; q < 8; q++) S += red[r * 8 + q];
        float iS = 1.0f / S;
        float* op = out + (size_t)(row0 + r) * KCAP + t8 * 4;
        #pragma unroll
        for (int j = 0; j < 16; j++) {
            float4 v = *(const float4*)(base + j * 32);
            float4 o;
            o.x = __expf((v.x - m) * invT) * iS;
            o.y = __expf((v.y - m) * invT) * iS;
            o.z = __expf((v.z - m) * invT) * iS;
            o.w = __expf((v.w - m) * invT) * iS;
            *(float4*)(op + j * 32) = o;
        }
    }
}

// ---------------- launcher ----------------
extern "C" void kernel_launch(void* const* d_in, const int* in_sizes, int n_in,
                              void* d_out, int out_size) {
    const float* x    = (const float*)d_in[0];
    const float* W    = (const float*)d_in[1];
    const float* A    = (const float*)d_in[2];
    const float* lT   = (const float*)d_in[3];
    const float* lc   = (const float*)d_in[4];
    const float* brun = (const float*)d_in[5];
    const void*  temp = d_in[6];
    const int B = in_sizes[0] / DDIM;   // 16384

    cudaFuncSetAttribute(k_main, cudaFuncAttributeMaxDynamicSharedMemorySize,
                         SMEM_MAIN_BYTES);

    k_scalars<<<1, 32>>>(lT, lc, temp);
    k_adiff<<<KCAP, 256>>>(A);
    k_prep<<<2, 256>>>(brun);
    k_norm<<<dim3(B / 128, 4), 256>>>(x, W, B);
    k_agree<<<(B + 255) / 256, 256>>>(B);
    k_main<<<B / 64, 512, SMEM_MAIN_BYTES>>>((float*)d_out);
}

// round 4
// speedup vs baseline: 2.0295x; 1.3109x over previous
#include <cuda_runtime.h>
#include <cstdint>

#define KCAP 512
#define DDIM 1024
#define BMAX 16384
#define PAD  520

// ---------------- device scratch (no allocations allowed) ----------------
__device__ __align__(16) float g_At[KCAP * KCAP];   // At[k*512+n] = tf32(0.1*A_diff[n][k])
__device__ float g_nsp[4 * BMAX];
__device__ float g_agr[BMAX];
__device__ __align__(16) float g_u1[KCAP];
__device__ __align__(16) float g_w1[KCAP];
__device__ float g_sc[2];                            // {1/T_eff, c}

// ---------------- helpers ----------------
__device__ __forceinline__ float blkMax256(float v, float* sc) {
    #pragma unroll
    for (int o = 16; o > 0; o >>= 1) v = fmaxf(v, __shfl_xor_sync(0xffffffffu, v, o));
    if ((threadIdx.x & 31) == 0) sc[threadIdx.x >> 5] = v;
    __syncthreads();
    float r = sc[0];
    #pragma unroll
    for (int i = 1; i < 8; i++) r = fmaxf(r, sc[i]);
    __syncthreads();
    return r;
}
__device__ __forceinline__ float blkSum256(float v, float* sc) {
    #pragma unroll
    for (int o = 16; o > 0; o >>= 1) v += __shfl_xor_sync(0xffffffffu, v, o);
    if ((threadIdx.x & 31) == 0) sc[threadIdx.x >> 5] = v;
    __syncthreads();
    float r = sc[0];
    #pragma unroll
    for (int i = 1; i < 8; i++) r += sc[i];
    __syncthreads();
    return r;
}
__device__ __forceinline__ uint32_t f2tf(float f) {
    uint32_t r;
    asm("cvt.rna.tf32.f32 %0, %1;" : "=r"(r) : "f"(f));
    return r;
}
// pack two floats to bf16x2: lo -> low half, hi -> high half
__device__ __forceinline__ unsigned packbf(float lo, float hi) {
    unsigned r;
    asm("cvt.rn.bf16x2.f32 %0, %1, %2;" : "=r"(r) : "f"(hi), "f"(lo));
    return r;
}
__device__ __forceinline__ void cp16(float* dst, const float* src) {
    unsigned s = (unsigned)__cvta_generic_to_shared(dst);
    asm volatile("cp.async.cg.shared.global [%0], [%1], 16;\n" :: "r"(s), "l"(src));
}
__device__ __forceinline__ void cpcommit() { asm volatile("cp.async.commit_group;\n"); }
template <int N>
__device__ __forceinline__ void cpwait() { asm volatile("cp.async.wait_group %0;\n" :: "n"(N)); }

#define MMA_TF32(c, a0, a1, a2, a3, b0, b1)                                            \
    asm volatile(                                                                       \
        "mma.sync.aligned.m16n8k8.row.col.f32.tf32.tf32.f32 "                           \
        "{%0,%1,%2,%3},{%4,%5,%6,%7},{%8,%9},{%0,%1,%2,%3};"                            \
        : "+f"((c)[0]), "+f"((c)[1]), "+f"((c)[2]), "+f"((c)[3])                        \
        : "r"(a0), "r"(a1), "r"(a2), "r"(a3), "r"(b0), "r"(b1))

#define MMA_BF16(c, a0, a1, a2, a3, b0, b1)                                            \
    asm volatile(                                                                       \
        "mma.sync.aligned.m16n8k16.row.col.f32.bf16.bf16.f32 "                          \
        "{%0,%1,%2,%3},{%4,%5,%6,%7},{%8,%9},{%0,%1,%2,%3};"                            \
        : "+f"((c)[0]), "+f"((c)[1]), "+f"((c)[2]), "+f"((c)[3])                        \
        : "r"(a0), "r"(a1), "r"(a2), "r"(a3), "r"(b0), "r"(b1))

// ---------------- P0: scalars ----------------
__global__ void k_scalars(const float* __restrict__ lT, const float* __restrict__ lc,
                          const void* __restrict__ tp) {
    if (threadIdx.x == 0) {
        unsigned w = *(const unsigned*)tp;
        float ft = __uint_as_float(w);
        float tempv = (fabsf(ft) > 1e-30f && fabsf(ft) < 1e30f) ? ft : (float)(int)w;
        float T = fminf(fmaxf(expf(lT[0]) * tempv, 0.05f), 10.0f);
        g_sc[0] = 1.0f / T;
        g_sc[1] = fminf(fmaxf(expf(lc[0]), 0.01f), 10.0f);
    }
}

// ---------------- P1: symmetric softmax -> At (transposed, scaled 0.1, tf32-rounded) ----------------
__global__ void __launch_bounds__(256) k_adiff(const float* __restrict__ A) {
    __shared__ float scr[8];
    const int j = blockIdx.x, tid = threadIdx.x;
    float v0 = 0.5f * (A[j * KCAP + tid]       + A[tid * KCAP + j]);
    float v1 = 0.5f * (A[j * KCAP + tid + 256] + A[(tid + 256) * KCAP + j]);
    float M = blkMax256(fmaxf(v0, v1), scr);
    float e0 = __expf(v0 - M), e1 = __expf(v1 - M);
    float S = blkSum256(e0 + e1, scr);
    float r = 0.1f / S;
    g_At[tid * KCAP + j]         = __uint_as_float(f2tf(e0 * r));
    g_At[(tid + 256) * KCAP + j] = __uint_as_float(f2tf(e1 * r));
}

// ---------------- P2: fold iteration 0 ----------------
__global__ void __launch_bounds__(256) k_prep(const float* __restrict__ brun) {
    __shared__ float br[KCAP];
    __shared__ float sg[KCAP];
    __shared__ float scr[8];
    const int tid = threadIdx.x;
    const float invT = g_sc[0];
    float v0 = brun[tid], v1 = brun[tid + 256];
    br[tid] = v0; br[tid + 256] = v1;
    float M = blkMax256(fmaxf(v0, v1), scr);
    float e0 = __expf((v0 - M) * invT), e1 = __expf((v1 - M) * invT);
    float S = blkSum256(e0 + e1, scr);
    float is = 1.0f / S;
    sg[tid] = e0 * is; sg[tid + 256] = e1 * is;
    __syncthreads();
    const int j = blockIdx.x * 256 + tid;
    float u = 0.0f, w = 0.0f;
    #pragma unroll 8
    for (int k = 0; k < KCAP; k++) {
        float at = g_At[k * KCAP + j];
        u = fmaf(br[k], at, u);
        w = fmaf(sg[k], at, w);
    }
    g_u1[j] = br[j] + u;
    g_w1[j] = sg[j] + w;
}

// ---------------- P3: fused x@W.T + row sum-of-squares via bf16 3-mma split ----------------
// Block tile 128 rows x 128 caps, 256 threads (8 warps), warp tile 32x64.
// grid (B/128, 4). Partial norm_sq -> g_nsp[by*B + row].
#define SSTRIDE 20   // b32 stride per row in bf16x2 units (16 data + 4 pad) -> conflict-free
__global__ void __launch_bounds__(256) k_norm(const float* __restrict__ x,
                                              const float* __restrict__ W, int B) {
    __shared__ unsigned XH[128 * SSTRIDE];
    __shared__ unsigned XL[128 * SSTRIDE];
    __shared__ unsigned WH[128 * SSTRIDE];
    __shared__ unsigned WL[128 * SSTRIDE];
    __shared__ float red2[128 * 2];

    const int tid  = threadIdx.x;
    const int lane = tid & 31;
    const int w    = tid >> 5;            // 0..7
    const int mrow = (w & 3) * 32;        // row stripe in block
    const int ncol = (w >> 2) * 64;       // col stripe in block
    const int row0 = blockIdx.x * 128;
    const int col0 = blockIdx.y * 128;

    // staging load mapping: thread -> (row tid>>1, half (tid&1)*16)
    const int srow = tid >> 1;
    const int soff = (tid & 1) * 16;
    const float* xp = x + (size_t)(row0 + srow) * DDIM + soff;
    const float* wp = W + (size_t)(col0 + srow) * DDIM + soff;
    const int sbase = srow * SSTRIDE + (tid & 1) * 8;

    float acc[2][8][4];
    #pragma unroll
    for (int mt = 0; mt < 2; mt++)
        #pragma unroll
        for (int nt = 0; nt < 8; nt++)
            #pragma unroll
            for (int q = 0; q < 4; q++) acc[mt][nt][q] = 0.0f;

    float4 rx[4], rw[4];
    #pragma unroll
    for (int i = 0; i < 4; i++) { rx[i] = *(const float4*)(xp + i * 4); rw[i] = *(const float4*)(wp + i * 4); }

    for (int kt = 0; kt < DDIM / 32; kt++) {
        __syncthreads();   // previous fragment reads complete
        // convert + store staged tile (hi/lo split)
        #pragma unroll
        for (int i = 0; i < 4; i++) {
            float4 v = rx[i];
            unsigned h0 = packbf(v.x, v.y);
            float l0 = v.x - __uint_as_float(h0 << 16);
            float l1 = v.y - __uint_as_float(h0 & 0xffff0000u);
            unsigned h1 = packbf(v.z, v.w);
            float l2 = v.z - __uint_as_float(h1 << 16);
            float l3 = v.w - __uint_as_float(h1 & 0xffff0000u);
            XH[sbase + i * 2]     = h0;
            XH[sbase + i * 2 + 1] = h1;
            XL[sbase + i * 2]     = packbf(l0, l1);
            XL[sbase + i * 2 + 1] = packbf(l2, l3);
            float4 u = rw[i];
            unsigned g0 = packbf(u.x, u.y);
            float m0 = u.x - __uint_as_float(g0 << 16);
            float m1 = u.y - __uint_as_float(g0 & 0xffff0000u);
            unsigned g1 = packbf(u.z, u.w);
            float m2 = u.z - __uint_as_float(g1 << 16);
            float m3 = u.w - __uint_as_float(g1 & 0xffff0000u);
            WH[sbase + i * 2]     = g0;
            WH[sbase + i * 2 + 1] = g1;
            WL[sbase + i * 2]     = packbf(m0, m1);
            WL[sbase + i * 2 + 1] = packbf(m2, m3);
        }
        __syncthreads();
        if (kt < DDIM / 32 - 1) {
            const float* xq = xp + (kt + 1) * 32;
            const float* wq = wp + (kt + 1) * 32;
            #pragma unroll
            for (int i = 0; i < 4; i++) { rx[i] = *(const float4*)(xq + i * 4); rw[i] = *(const float4*)(wq + i * 4); }
        }
        // two k16 chunks
        #pragma unroll
        for (int c = 0; c < 2; c++) {
            const int kb = c * 8 + (lane & 3);
            unsigned ah[2][4], al[2][4];
            #pragma unroll
            for (int mt = 0; mt < 2; mt++) {
                int ra = (mrow + mt * 16 + (lane >> 2)) * SSTRIDE;
                ah[mt][0] = XH[ra + kb];
                ah[mt][1] = XH[ra + 8 * SSTRIDE + kb];
                ah[mt][2] = XH[ra + kb + 4];
                ah[mt][3] = XH[ra + 8 * SSTRIDE + kb + 4];
                al[mt][0] = XL[ra + kb];
                al[mt][1] = XL[ra + 8 * SSTRIDE + kb];
                al[mt][2] = XL[ra + kb + 4];
                al[mt][3] = XL[ra + 8 * SSTRIDE + kb + 4];
            }
            #pragma unroll
            for (int nt = 0; nt < 8; nt++) {
                int rb = (ncol + nt * 8 + (lane >> 2)) * SSTRIDE;
                unsigned bh0 = WH[rb + kb], bh1 = WH[rb + kb + 4];
                unsigned bl0 = WL[rb + kb], bl1 = WL[rb + kb + 4];
                #pragma unroll
                for (int mt = 0; mt < 2; mt++) {
                    MMA_BF16(acc[mt][nt], ah[mt][0], ah[mt][1], ah[mt][2], ah[mt][3], bh0, bh1);
                    MMA_BF16(acc[mt][nt], ah[mt][0], ah[mt][1], ah[mt][2], ah[mt][3], bl0, bl1);
                    MMA_BF16(acc[mt][nt], al[mt][0], al[mt][1], al[mt][2], al[mt][3], bh0, bh1);
                }
            }
        }
    }

    // epilogue: per-row sum of squares over this warp's 64 cols
    #pragma unroll
    for (int mt = 0; mt < 2; mt++) {
        #pragma unroll
        for (int h = 0; h < 2; h++) {
            float s = 0.0f;
            #pragma unroll
            for (int nt = 0; nt < 8; nt++) {
                float a = acc[mt][nt][2 * h], b = acc[mt][nt][2 * h + 1];
                s = fmaf(a, a, fmaf(b, b, s));
            }
            s += __shfl_xor_sync(0xffffffffu, s, 1);
            s += __shfl_xor_sync(0xffffffffu, s, 2);
            if ((lane & 3) == 0) {
                int rloc = mrow + mt * 16 + (lane >> 2) + h * 8;
                red2[rloc * 2 + (w >> 2)] = s;
            }
        }
    }
    __syncthreads();
    if (tid < 128) {
        float s = red2[tid * 2] + red2[tid * 2 + 1];
        g_nsp[(size_t)blockIdx.y * B + row0 + tid] = s;
    }
}

// ---------------- P4: agreement ----------------
__global__ void k_agree(int B) {
    int i = blockIdx.x * 256 + threadIdx.x;
    if (i < B) {
        float c = g_sc[1];
        float ns = g_nsp[i] + g_nsp[B + i] + g_nsp[2 * B + i] + g_nsp[3 * B + i];
        ns = fmaxf(ns, 1e-10f);
        float sc2 = c * ns / (1.0f + c * ns);
        g_agr[i] = sc2 * sqrtf(ns);
    }
}

// ---------------- MAIN: 4 routing iterations, tf32 tensor-core diffusion GEMM (unchanged) ----------------
#define SMEM_MAIN_FLOATS (64 * PAD + 2 * 8 * PAD + 512 + 64)
#define SMEM_MAIN_BYTES  (SMEM_MAIN_FLOATS * 4)

__global__ void __launch_bounds__(512, 1) k_main(float* __restrict__ out) {
    extern __shared__ float sm[];
    float* b_s  = sm;                       // [64][PAD]
    float* slab = sm + 64 * PAD;            // 2 x [8][PAD]
    float* red  = slab + 2 * 8 * PAD;       // [512]
    float* agrs = red + 512;                // [64]

    const int tid  = threadIdx.x;
    const int lane = tid & 31;
    const int wrp  = tid >> 5;              // 0..15
    const int rbase = (wrp & 3) * 16;       // row stripe
    const int nbase = (wrp >> 2) * 128;     // col stripe
    const int row0 = blockIdx.x * 64;
    const float invT = g_sc[0];

    const int r  = tid >> 3;                // 0..63
    const int t8 = tid & 7;
    float* base = b_s + r * PAD + t8 * 4;

    if (tid < 64) agrs[tid] = g_agr[row0 + tid];
    float uj = g_u1[tid];
    float wj = g_w1[tid];
    __syncthreads();
    #pragma unroll 8
    for (int r2 = 0; r2 < 64; r2++)
        b_s[r2 * PAD + tid] = fmaf(agrs[r2], wj, uj);
    __syncthreads();

    for (int it = 0; it < 4; it++) {
        {
            const float* src = g_At;
            float* dst = slab;
            #pragma unroll
            for (int q = 0; q < 2; q++) {
                int lin = tid + q * 512;
                int rowk = lin >> 7, c4 = (lin & 127) * 4;
                cp16(dst + rowk * PAD + c4, src + rowk * KCAP + c4);
            }
            cpcommit();
        }

        float mx = -3.4e38f;
        #pragma unroll
        for (int j = 0; j < 16; j++) {
            float4 v = *(const float4*)(base + j * 32);
            mx = fmaxf(mx, fmaxf(fmaxf(v.x, v.y), fmaxf(v.z, v.w)));
        }
        red[tid] = mx; __syncthreads();
        float m = red[r * 8];
        #pragma unroll
        for (int q = 1; q < 8; q++) m = fmaxf(m, red[r * 8 + q]);
        __syncthreads();
        float s = 0.0f;
        #pragma unroll
        for (int j = 0; j < 16; j++) {
            float4 v = *(const float4*)(base + j * 32);
            s += __expf((v.x - m) * invT) + __expf((v.y - m) * invT)
               + __expf((v.z - m) * invT) + __expf((v.w - m) * invT);
        }
        red[tid] = s; __syncthreads();
        float S = red[r * 8];
        #pragma unroll
        for (int q = 1; q < 8; q++) S += red[r * 8 + q];
        float aS = agrs[r] / S;
        #pragma unroll
        for (int j = 0; j < 16; j++) {
            float4 v = *(const float4*)(base + j * 32);
            v.x = fmaf(aS, __expf((v.x - m) * invT), v.x);
            v.y = fmaf(aS, __expf((v.y - m) * invT), v.y);
            v.z = fmaf(aS, __expf((v.z - m) * invT), v.z);
            v.w = fmaf(aS, __expf((v.w - m) * invT), v.w);
            *(float4*)(base + j * 32) = v;
        }
        __syncthreads();

        float acc[16][4];
        #pragma unroll
        for (int t = 0; t < 16; t++)
            #pragma unroll
            for (int q = 0; q < 4; q++) acc[t][q] = 0.0f;

        for (int kc = 0; kc < 64; kc++) {
            if (kc < 63) {
                const float* src = g_At + (kc + 1) * 8 * KCAP;
                float* dst = slab + ((kc + 1) & 1) * 8 * PAD;
                #pragma unroll
                for (int q = 0; q < 2; q++) {
                    int lin = tid + q * 512;
                    int rowk = lin >> 7, c4 = (lin & 127) * 4;
                    cp16(dst + rowk * PAD + c4, src + rowk * KCAP + c4);
                }
                cpcommit();
                cpwait<1>();
            } else {
                cpwait<0>();
            }
            __syncthreads();

            const float* sb = slab + (kc & 1) * 8 * PAD;
            const int k0 = kc * 8;

            const float* ap = b_s + (rbase + (lane >> 2)) * PAD + k0 + (lane & 3);
            float v00 = ap[0];
            float v10 = ap[8 * PAD];
            float v01 = ap[4];
            float v11 = ap[8 * PAD + 4];
            uint32_t h0 = f2tf(v00), h1 = f2tf(v10), h2 = f2tf(v01), h3 = f2tf(v11);
            uint32_t l0 = f2tf(v00 - __uint_as_float(h0));
            uint32_t l1 = f2tf(v10 - __uint_as_float(h1));
            uint32_t l2 = f2tf(v01 - __uint_as_float(h2));
            uint32_t l3 = f2tf(v11 - __uint_as_float(h3));

            const float* bp0 = sb + (lane & 3) * PAD + nbase + (lane >> 2);
            const float* bp1 = bp0 + 4 * PAD;
            #pragma unroll
            for (int t = 0; t < 16; t++) {
                uint32_t b0 = __float_as_uint(bp0[t * 8]);
                uint32_t b1 = __float_as_uint(bp1[t * 8]);
                MMA_TF32(acc[t], h0, h1, h2, h3, b0, b1);
                MMA_TF32(acc[t], l0, l1, l2, l3, b0, b1);
            }
            __syncthreads();
        }

        float* ep = b_s + (rbase + (lane >> 2)) * PAD + nbase + 2 * (lane & 3);
        #pragma unroll
        for (int t = 0; t < 16; t++) {
            float* p = ep + t * 8;
            p[0]           += acc[t][0];
            p[1]           += acc[t][1];
            p[8 * PAD]     += acc[t][2];
            p[8 * PAD + 1] += acc[t][3];
        }
        __syncthreads();
    }

    {
        float mx = -3.4e38f;
        #pragma unroll
        for (int j = 0; j < 16; j++) {
            float4 v = *(const float4*)(base + j * 32);
            mx = fmaxf(mx, fmaxf(fmaxf(v.x, v.y), fmaxf(v.z, v.w)));
        }
        red[tid] = mx; __syncthreads();
        float m = red[r * 8];
        #pragma unroll
        for (int q = 1; q < 8; q++) m = fmaxf(m, red[r * 8 + q]);
        __syncthreads();
        float s = 0.0f;
        #pragma unroll
        for (int j = 0; j < 16; j++) {
            float4 v = *(const float4*)(base + j * 32);
            s += __expf((v.x - m) * invT) + __expf((v.y - m) * invT)
               + __expf((v.z - m) * invT) + __expf((v.w - m) * invT);
        }
        red[tid] = s; __syncthreads();
        float S = red[r * 8];
        #pragma unroll
        for (int q = 1; q < 8; q++) S += red[r * 8 + q];
        float iS = 1.0f / S;
        float* op = out + (size_t)(row0 + r) * KCAP + t8 * 4;
        #pragma unroll
        for (int j = 0; j < 16; j++) {
            float4 v = *(const float4*)(base + j * 32);
            float4 o;
            o.x = __expf((v.x - m) * invT) * iS;
            o.y = __expf((v.y - m) * invT) * iS;
            o.z = __expf((v.z - m) * invT) * iS;
            o.w = __expf((v.w - m) * invT) * iS;
            *(float4*)(op + j * 32) = o;
        }
    }
}

// ---------------- launcher ----------------
extern "C" void kernel_launch(void* const* d_in, const int* in_sizes, int n_in,
                              void* d_out, int out_size) {
    const float* x    = (const float*)d_in[0];
    const float* W    = (const float*)d_in[1];
    const float* A    = (const float*)d_in[2];
    const float* lT   = (const float*)d_in[3];
    const float* lc   = (const float*)d_in[4];
    const float* brun = (const float*)d_in[5];
    const void*  temp = d_in[6];
    const int B = in_sizes[0] / DDIM;   // 16384

    cudaFuncSetAttribute(k_main, cudaFuncAttributeMaxDynamicSharedMemorySize,
                         SMEM_MAIN_BYTES);

    k_scalars<<<1, 32>>>(lT, lc, temp);
    k_adiff<<<KCAP, 256>>>(A);
    k_prep<<<2, 256>>>(brun);
    k_norm<<<dim3(B / 128, 4), 256>>>(x, W, B);
    k_agree<<<(B + 255) / 256, 256>>>(B);
    k_main<<<B / 64, 512, SMEM_MAIN_BYTES>>>((float*)d_out);
}

// round 5
// speedup vs baseline: 2.3259x; 1.1461x over previous
#include <cuda_runtime.h>
#include <cstdint>

#define KCAP 512
#define DDIM 1024
#define BMAX 16384
#define PAD  520
#define PADU 520

// ---------------- device scratch (no allocations allowed) ----------------
__device__ __align__(16) float    g_At[KCAP * KCAP];        // fp32 0.1*A_diff^T (for k_prep)
__device__ __align__(16) unsigned g_AtH[(KCAP / 2) * KCAP]; // bf16x2 hi, [kpair][n]
__device__ __align__(16) unsigned g_AtL[(KCAP / 2) * KCAP]; // bf16x2 lo, [kpair][n]
__device__ float g_nsp[4 * BMAX];
__device__ float g_agr[BMAX];
__device__ __align__(16) float g_u1[KCAP];
__device__ __align__(16) float g_w1[KCAP];
__device__ float g_sc[2];                                   // {1/T_eff, c}

// ---------------- helpers ----------------
__device__ __forceinline__ float blkMax256(float v, float* sc) {
    #pragma unroll
    for (int o = 16; o > 0; o >>= 1) v = fmaxf(v, __shfl_xor_sync(0xffffffffu, v, o));
    if ((threadIdx.x & 31) == 0) sc[threadIdx.x >> 5] = v;
    __syncthreads();
    float r = sc[0];
    #pragma unroll
    for (int i = 1; i < 8; i++) r = fmaxf(r, sc[i]);
    __syncthreads();
    return r;
}
__device__ __forceinline__ float blkSum256(float v, float* sc) {
    #pragma unroll
    for (int o = 16; o > 0; o >>= 1) v += __shfl_xor_sync(0xffffffffu, v, o);
    if ((threadIdx.x & 31) == 0) sc[threadIdx.x >> 5] = v;
    __syncthreads();
    float r = sc[0];
    #pragma unroll
    for (int i = 1; i < 8; i++) r += sc[i];
    __syncthreads();
    return r;
}
// pack two floats to bf16x2: first arg -> low half, second -> high half
__device__ __forceinline__ unsigned packbf(float lo, float hi) {
    unsigned r;
    asm("cvt.rn.bf16x2.f32 %0, %1, %2;" : "=r"(r) : "f"(hi), "f"(lo));
    return r;
}
__device__ __forceinline__ float lo16f(unsigned h) { return __uint_as_float(h << 16); }
__device__ __forceinline__ float hi16f(unsigned h) { return __uint_as_float(h & 0xffff0000u); }

__device__ __forceinline__ void cp16(void* dst, const void* src) {
    unsigned s = (unsigned)__cvta_generic_to_shared(dst);
    asm volatile("cp.async.cg.shared.global [%0], [%1], 16;\n" :: "r"(s), "l"(src));
}
__device__ __forceinline__ void cpcommit() { asm volatile("cp.async.commit_group;\n"); }
template <int N>
__device__ __forceinline__ void cpwait() { asm volatile("cp.async.wait_group %0;\n" :: "n"(N)); }

#define MMA_BF16(c, a0, a1, a2, a3, b0, b1)                                            \
    asm volatile(                                                                       \
        "mma.sync.aligned.m16n8k16.row.col.f32.bf16.bf16.f32 "                          \
        "{%0,%1,%2,%3},{%4,%5,%6,%7},{%8,%9},{%0,%1,%2,%3};"                            \
        : "+f"((c)[0]), "+f"((c)[1]), "+f"((c)[2]), "+f"((c)[3])                        \
        : "r"(a0), "r"(a1), "r"(a2), "r"(a3), "r"(b0), "r"(b1))

// ---------------- P0: scalars ----------------
__global__ void k_scalars(const float* __restrict__ lT, const float* __restrict__ lc,
                          const void* __restrict__ tp) {
    if (threadIdx.x == 0) {
        unsigned w = *(const unsigned*)tp;
        float ft = __uint_as_float(w);
        float tempv = (fabsf(ft) > 1e-30f && fabsf(ft) < 1e30f) ? ft : (float)(int)w;
        float T = fminf(fmaxf(expf(lT[0]) * tempv, 0.05f), 10.0f);
        g_sc[0] = 1.0f / T;
        g_sc[1] = fminf(fmaxf(expf(lc[0]), 0.01f), 10.0f);
    }
}

// ---------------- P1: symmetric softmax -> At fp32 + bf16x2 hi/lo packed ----------------
__global__ void __launch_bounds__(256) k_adiff(const float* __restrict__ A) {
    __shared__ float scr[8];
    __shared__ float col[KCAP];
    const int j = blockIdx.x, tid = threadIdx.x;
    float v0 = 0.5f * (A[j * KCAP + tid]       + A[tid * KCAP + j]);
    float v1 = 0.5f * (A[j * KCAP + tid + 256] + A[(tid + 256) * KCAP + j]);
    float M = blkMax256(fmaxf(v0, v1), scr);
    float e0 = __expf(v0 - M), e1 = __expf(v1 - M);
    float S = blkSum256(e0 + e1, scr);
    float r = 0.1f / S;
    float a0 = e0 * r, a1 = e1 * r;
    g_At[tid * KCAP + j]         = a0;
    g_At[(tid + 256) * KCAP + j] = a1;
    col[tid] = a0; col[tid + 256] = a1;
    __syncthreads();
    // pack k-pairs: g_AtH/[L][kpair*512 + n]
    float p0 = col[2 * tid], p1 = col[2 * tid + 1];
    unsigned h = packbf(p0, p1);
    unsigned l = packbf(p0 - lo16f(h), p1 - hi16f(h));
    g_AtH[tid * KCAP + j] = h;
    g_AtL[tid * KCAP + j] = l;
}

// ---------------- P2: fold iteration 0 ----------------
__global__ void __launch_bounds__(256) k_prep(const float* __restrict__ brun) {
    __shared__ float br[KCAP];
    __shared__ float sg[KCAP];
    __shared__ float scr[8];
    const int tid = threadIdx.x;
    const float invT = g_sc[0];
    float v0 = brun[tid], v1 = brun[tid + 256];
    br[tid] = v0; br[tid + 256] = v1;
    float M = blkMax256(fmaxf(v0, v1), scr);
    float e0 = __expf((v0 - M) * invT), e1 = __expf((v1 - M) * invT);
    float S = blkSum256(e0 + e1, scr);
    float is = 1.0f / S;
    sg[tid] = e0 * is; sg[tid + 256] = e1 * is;
    __syncthreads();
    const int j = blockIdx.x * 256 + tid;
    float u = 0.0f, w = 0.0f;
    #pragma unroll 8
    for (int k = 0; k < KCAP; k++) {
        float at = g_At[k * KCAP + j];
        u = fmaf(br[k], at, u);
        w = fmaf(sg[k], at, w);
    }
    g_u1[j] = br[j] + u;
    g_w1[j] = sg[j] + w;
}

// ---------------- P3: fused x@W.T + row sum-of-squares via bf16 3-mma split ----------------
#define SSTRIDE 20
__global__ void __launch_bounds__(256) k_norm(const float* __restrict__ x,
                                              const float* __restrict__ W, int B) {
    __shared__ unsigned XH[128 * SSTRIDE];
    __shared__ unsigned XL[128 * SSTRIDE];
    __shared__ unsigned WH[128 * SSTRIDE];
    __shared__ unsigned WL[128 * SSTRIDE];
    __shared__ float red2[128 * 2];

    const int tid  = threadIdx.x;
    const int lane = tid & 31;
    const int w    = tid >> 5;
    const int mrow = (w & 3) * 32;
    const int ncol = (w >> 2) * 64;
    const int row0 = blockIdx.x * 128;
    const int col0 = blockIdx.y * 128;

    const int srow = tid >> 1;
    const int soff = (tid & 1) * 16;
    const float* xp = x + (size_t)(row0 + srow) * DDIM + soff;
    const float* wp = W + (size_t)(col0 + srow) * DDIM + soff;
    const int sbase = srow * SSTRIDE + (tid & 1) * 8;

    float acc[2][8][4];
    #pragma unroll
    for (int mt = 0; mt < 2; mt++)
        #pragma unroll
        for (int nt = 0; nt < 8; nt++)
            #pragma unroll
            for (int q = 0; q < 4; q++) acc[mt][nt][q] = 0.0f;

    float4 rx[4], rw[4];
    #pragma unroll
    for (int i = 0; i < 4; i++) { rx[i] = *(const float4*)(xp + i * 4); rw[i] = *(const float4*)(wp + i * 4); }

    for (int kt = 0; kt < DDIM / 32; kt++) {
        __syncthreads();
        #pragma unroll
        for (int i = 0; i < 4; i++) {
            float4 v = rx[i];
            unsigned h0 = packbf(v.x, v.y);
            float l0 = v.x - lo16f(h0);
            float l1 = v.y - hi16f(h0);
            unsigned h1 = packbf(v.z, v.w);
            float l2 = v.z - lo16f(h1);
            float l3 = v.w - hi16f(h1);
            XH[sbase + i * 2]     = h0;
            XH[sbase + i * 2 + 1] = h1;
            XL[sbase + i * 2]     = packbf(l0, l1);
            XL[sbase + i * 2 + 1] = packbf(l2, l3);
            float4 u = rw[i];
            unsigned g0 = packbf(u.x, u.y);
            float m0 = u.x - lo16f(g0);
            float m1 = u.y - hi16f(g0);
            unsigned g1 = packbf(u.z, u.w);
            float m2 = u.z - lo16f(g1);
            float m3 = u.w - hi16f(g1);
            WH[sbase + i * 2]     = g0;
            WH[sbase + i * 2 + 1] = g1;
            WL[sbase + i * 2]     = packbf(m0, m1);
            WL[sbase + i * 2 + 1] = packbf(m2, m3);
        }
        __syncthreads();
        if (kt < DDIM / 32 - 1) {
            const float* xq = xp + (kt + 1) * 32;
            const float* wq = wp + (kt + 1) * 32;
            #pragma unroll
            for (int i = 0; i < 4; i++) { rx[i] = *(const float4*)(xq + i * 4); rw[i] = *(const float4*)(wq + i * 4); }
        }
        #pragma unroll
        for (int c = 0; c < 2; c++) {
            const int kb = c * 8 + (lane & 3);
            unsigned ah[2][4], al[2][4];
            #pragma unroll
            for (int mt = 0; mt < 2; mt++) {
                int ra = (mrow + mt * 16 + (lane >> 2)) * SSTRIDE;
                ah[mt][0] = XH[ra + kb];
                ah[mt][1] = XH[ra + 8 * SSTRIDE + kb];
                ah[mt][2] = XH[ra + kb + 4];
                ah[mt][3] = XH[ra + 8 * SSTRIDE + kb + 4];
                al[mt][0] = XL[ra + kb];
                al[mt][1] = XL[ra + 8 * SSTRIDE + kb];
                al[mt][2] = XL[ra + kb + 4];
                al[mt][3] = XL[ra + 8 * SSTRIDE + kb + 4];
            }
            #pragma unroll
            for (int nt = 0; nt < 8; nt++) {
                int rb = (ncol + nt * 8 + (lane >> 2)) * SSTRIDE;
                unsigned bh0 = WH[rb + kb], bh1 = WH[rb + kb + 4];
                unsigned bl0 = WL[rb + kb], bl1 = WL[rb + kb + 4];
                #pragma unroll
                for (int mt = 0; mt < 2; mt++) {
                    MMA_BF16(acc[mt][nt], ah[mt][0], ah[mt][1], ah[mt][2], ah[mt][3], bh0, bh1);
                    MMA_BF16(acc[mt][nt], ah[mt][0], ah[mt][1], ah[mt][2], ah[mt][3], bl0, bl1);
                    MMA_BF16(acc[mt][nt], al[mt][0], al[mt][1], al[mt][2], al[mt][3], bh0, bh1);
                }
            }
        }
    }

    #pragma unroll
    for (int mt = 0; mt < 2; mt++) {
        #pragma unroll
        for (int h = 0; h < 2; h++) {
            float s = 0.0f;
            #pragma unroll
            for (int nt = 0; nt < 8; nt++) {
                float a = acc[mt][nt][2 * h], b = acc[mt][nt][2 * h + 1];
                s = fmaf(a, a, fmaf(b, b, s));
            }
            s += __shfl_xor_sync(0xffffffffu, s, 1);
            s += __shfl_xor_sync(0xffffffffu, s, 2);
            if ((lane & 3) == 0) {
                int rloc = mrow + mt * 16 + (lane >> 2) + h * 8;
                red2[rloc * 2 + (w >> 2)] = s;
            }
        }
    }
    __syncthreads();
    if (tid < 128) {
        float s = red2[tid * 2] + red2[tid * 2 + 1];
        g_nsp[(size_t)blockIdx.y * B + row0 + tid] = s;
    }
}

// ---------------- P4: agreement ----------------
__global__ void k_agree(int B) {
    int i = blockIdx.x * 256 + threadIdx.x;
    if (i < B) {
        float c = g_sc[1];
        float ns = g_nsp[i] + g_nsp[B + i] + g_nsp[2 * B + i] + g_nsp[3 * B + i];
        ns = fmaxf(ns, 1e-10f);
        float sc2 = c * ns / (1.0f + c * ns);
        g_agr[i] = sc2 * sqrtf(ns);
    }
}

// ---------------- MAIN: 4 routing iterations, bf16 3-mma diffusion GEMM ----------------
// smem: b_s[64*PAD] f32 | slabH 2x[8][PADU] u32 | slabL 2x[8][PADU] u32 | red[512] | agrs[64]
#define SMEM_MAIN_FLOATS (64 * PAD + 4 * 8 * PADU + 512 + 64)
#define SMEM_MAIN_BYTES  (SMEM_MAIN_FLOATS * 4)

__global__ void __launch_bounds__(512, 1) k_main(float* __restrict__ out) {
    extern __shared__ float sm[];
    float*    b_s   = sm;                                  // [64][PAD]
    unsigned* slabH = (unsigned*)(sm + 64 * PAD);          // 2 x [8][PADU]
    unsigned* slabL = slabH + 2 * 8 * PADU;                // 2 x [8][PADU]
    float*    red   = (float*)(slabL + 2 * 8 * PADU);      // [512]
    float*    agrs  = red + 512;                           // [64]

    const int tid  = threadIdx.x;
    const int lane = tid & 31;
    const int wrp  = tid >> 5;               // 0..15
    const int rbase = (wrp & 3) * 16;        // row stripe
    const int nbase = (wrp >> 2) * 128;      // col stripe
    const int row0 = blockIdx.x * 64;
    const float invT = g_sc[0];

    const int r  = tid >> 3;                 // 0..63
    const int t8 = tid & 7;
    float* base = b_s + r * PAD + t8 * 4;

    if (tid < 64) agrs[tid] = g_agr[row0 + tid];
    float uj = g_u1[tid];
    float wj = g_w1[tid];
    __syncthreads();
    #pragma unroll 8
    for (int r2 = 0; r2 < 64; r2++)
        b_s[r2 * PAD + tid] = fmaf(agrs[r2], wj, uj);
    __syncthreads();

    for (int it = 0; it < 4; it++) {
        // prefetch k16 chunk 0 (H+L) — overlaps with softmax
        {
            int rowk = tid >> 7, c4 = (tid & 127) * 4;
            cp16(slabH + rowk * PADU + c4,             g_AtH + rowk * KCAP + c4);
            cp16(slabH + (rowk + 4) * PADU + c4,       g_AtH + (rowk + 4) * KCAP + c4);
            cp16(slabL + rowk * PADU + c4,             g_AtL + rowk * KCAP + c4);
            cp16(slabL + (rowk + 4) * PADU + c4,       g_AtL + (rowk + 4) * KCAP + c4);
            cpcommit();
        }

        // ---- b += a * softmax(b/T) ----
        float mx = -3.4e38f;
        #pragma unroll
        for (int j = 0; j < 16; j++) {
            float4 v = *(const float4*)(base + j * 32);
            mx = fmaxf(mx, fmaxf(fmaxf(v.x, v.y), fmaxf(v.z, v.w)));
        }
        red[tid] = mx; __syncthreads();
        float m = red[r * 8];
        #pragma unroll
        for (int q = 1; q < 8; q++) m = fmaxf(m, red[r * 8 + q]);
        __syncthreads();
        float s = 0.0f;
        #pragma unroll
        for (int j = 0; j < 16; j++) {
            float4 v = *(const float4*)(base + j * 32);
            s += __expf((v.x - m) * invT) + __expf((v.y - m) * invT)
               + __expf((v.z - m) * invT) + __expf((v.w - m) * invT);
        }
        red[tid] = s; __syncthreads();
        float S = red[r * 8];
        #pragma unroll
        for (int q = 1; q < 8; q++) S += red[r * 8 + q];
        float aS = agrs[r] / S;
        #pragma unroll
        for (int j = 0; j < 16; j++) {
            float4 v = *(const float4*)(base + j * 32);
            v.x = fmaf(aS, __expf((v.x - m) * invT), v.x);
            v.y = fmaf(aS, __expf((v.y - m) * invT), v.y);
            v.z = fmaf(aS, __expf((v.z - m) * invT), v.z);
            v.w = fmaf(aS, __expf((v.w - m) * invT), v.w);
            *(float4*)(base + j * 32) = v;
        }
        __syncthreads();

        // ---- d = b @ At via bf16 3-mma split ----
        float acc[16][4];
        #pragma unroll
        for (int t = 0; t < 16; t++)
            #pragma unroll
            for (int q = 0; q < 4; q++) acc[t][q] = 0.0f;

        for (int kc = 0; kc < 32; kc++) {
            if (kc < 31) {
                int buf = (kc + 1) & 1;
                int rowk = tid >> 7, c4 = (tid & 127) * 4;
                const unsigned* srcH = g_AtH + (kc + 1) * 8 * KCAP;
                const unsigned* srcL = g_AtL + (kc + 1) * 8 * KCAP;
                unsigned* dstH = slabH + buf * 8 * PADU;
                unsigned* dstL = slabL + buf * 8 * PADU;
                cp16(dstH + rowk * PADU + c4,       srcH + rowk * KCAP + c4);
                cp16(dstH + (rowk + 4) * PADU + c4, srcH + (rowk + 4) * KCAP + c4);
                cp16(dstL + rowk * PADU + c4,       srcL + rowk * KCAP + c4);
                cp16(dstL + (rowk + 4) * PADU + c4, srcL + (rowk + 4) * KCAP + c4);
                cpcommit();
                cpwait<1>();
            } else {
                cpwait<0>();
            }
            __syncthreads();

            const unsigned* sH = slabH + (kc & 1) * 8 * PADU;
            const unsigned* sL = slabL + (kc & 1) * 8 * PADU;
            const int k0 = kc * 16;

            // A fragments: rows rbase+(lane>>2), +8; k pairs (lane&3)*2, +8
            const float* ap = b_s + (rbase + (lane >> 2)) * PAD + k0 + (lane & 3) * 2;
            float2 v00 = *(const float2*)ap;
            float2 v10 = *(const float2*)(ap + 8 * PAD);
            float2 v01 = *(const float2*)(ap + 8);
            float2 v11 = *(const float2*)(ap + 8 * PAD + 8);
            unsigned ah0 = packbf(v00.x, v00.y);
            unsigned ah1 = packbf(v10.x, v10.y);
            unsigned ah2 = packbf(v01.x, v01.y);
            unsigned ah3 = packbf(v11.x, v11.y);
            unsigned al0 = packbf(v00.x - lo16f(ah0), v00.y - hi16f(ah0));
            unsigned al1 = packbf(v10.x - lo16f(ah1), v10.y - hi16f(ah1));
            unsigned al2 = packbf(v01.x - lo16f(ah2), v01.y - hi16f(ah2));
            unsigned al3 = packbf(v11.x - lo16f(ah3), v11.y - hi16f(ah3));

            const unsigned* bpH0 = sH + (lane & 3) * PADU + nbase + (lane >> 2);
            const unsigned* bpH1 = bpH0 + 4 * PADU;
            const unsigned* bpL0 = sL + (lane & 3) * PADU + nbase + (lane >> 2);
            const unsigned* bpL1 = bpL0 + 4 * PADU;
            #pragma unroll
            for (int t = 0; t < 16; t++) {
                unsigned bh0 = bpH0[t * 8], bh1 = bpH1[t * 8];
                unsigned bl0 = bpL0[t * 8], bl1 = bpL1[t * 8];
                MMA_BF16(acc[t], ah0, ah1, ah2, ah3, bh0, bh1);
                MMA_BF16(acc[t], ah0, ah1, ah2, ah3, bl0, bl1);
                MMA_BF16(acc[t], al0, al1, al2, al3, bh0, bh1);
            }
            __syncthreads();
        }

        // ---- b += d ----
        float* ep = b_s + (rbase + (lane >> 2)) * PAD + nbase + 2 * (lane & 3);
        #pragma unroll
        for (int t = 0; t < 16; t++) {
            float* p = ep + t * 8;
            p[0]           += acc[t][0];
            p[1]           += acc[t][1];
            p[8 * PAD]     += acc[t][2];
            p[8 * PAD + 1] += acc[t][3];
        }
        __syncthreads();
    }

    // ---- theta = softmax(b/T) -> out ----
    {
        float mx = -3.4e38f;
        #pragma unroll
        for (int j = 0; j < 16; j++) {
            float4 v = *(const float4*)(base + j * 32);
            mx = fmaxf(mx, fmaxf(fmaxf(v.x, v.y), fmaxf(v.z, v.w)));
        }
        red[tid] = mx; __syncthreads();
        float m = red[r * 8];
        #pragma unroll
        for (int q = 1; q < 8; q++) m = fmaxf(m, red[r * 8 + q]);
        __syncthreads();
        float s = 0.0f;
        #pragma unroll
        for (int j = 0; j < 16; j++) {
            float4 v = *(const float4*)(base + j * 32);
            s += __expf((v.x - m) * invT) + __expf((v.y - m) * invT)
               + __expf((v.z - m) * invT) + __expf((v.w - m) * invT);
        }
        red[tid] = s; __syncthreads();
        float S = red[r * 8];
        #pragma unroll
        for (int q = 1; q < 8; q++) S += red[r * 8 + q];
        float iS = 1.0f / S;
        float* op = out + (size_t)(row0 + r) * KCAP + t8 * 4;
        #pragma unroll
        for (int j = 0; j < 16; j++) {
            float4 v = *(const float4*)(base + j * 32);
            float4 o;
            o.x = __expf((v.x - m) * invT) * iS;
            o.y = __expf((v.y - m) * invT) * iS;
            o.z = __expf((v.z - m) * invT) * iS;
            o.w = __expf((v.w - m) * invT) * iS;
            *(float4*)(op + j * 32) = o;
        }
    }
}

// ---------------- launcher ----------------
extern "C" void kernel_launch(void* const* d_in, const int* in_sizes, int n_in,
                              void* d_out, int out_size) {
    const float* x    = (const float*)d_in[0];
    const float* W    = (const float*)d_in[1];
    const float* A    = (const float*)d_in[2];
    const float* lT   = (const float*)d_in[3];
    const float* lc   = (const float*)d_in[4];
    const float* brun = (const float*)d_in[5];
    const void*  temp = d_in[6];
    const int B = in_sizes[0] / DDIM;   // 16384

    cudaFuncSetAttribute(k_main, cudaFuncAttributeMaxDynamicSharedMemorySize,
                         SMEM_MAIN_BYTES);

    k_scalars<<<1, 32>>>(lT, lc, temp);
    k_adiff<<<KCAP, 256>>>(A);
    k_prep<<<2, 256>>>(brun);
    k_norm<<<dim3(B / 128, 4), 256>>>(x, W, B);
    k_agree<<<(B + 255) / 256, 256>>>(B);
    k_main<<<B / 64, 512, SMEM_MAIN_BYTES>>>((float*)d_out);
}

// round 6
// speedup vs baseline: 3.1446x; 1.3520x over previous
#include <cuda_runtime.h>
#include <cuda_fp16.h>
#include <cstdint>

#define KCAP 512
#define DDIM 1024
#define BMAX 16384
#define PAD  520
#define PADU 520

// ---------------- device scratch (no allocations allowed) ----------------
__device__ __align__(16) float    g_At[KCAP * KCAP];        // fp32 0.1*A_diff^T (for k_prep)
__device__ __align__(16) unsigned g_AtH[(KCAP / 2) * KCAP]; // f16x2 packed k-pairs, [kpair][n]
__device__ float g_nsp[4 * BMAX];
__device__ float g_agr[BMAX];
__device__ __align__(16) float g_u1[KCAP];
__device__ __align__(16) float g_w1[KCAP];
__device__ float g_sc[2];                                   // {1/T_eff, c}

// ---------------- helpers ----------------
__device__ __forceinline__ float blkMax256(float v, float* sc) {
    #pragma unroll
    for (int o = 16; o > 0; o >>= 1) v = fmaxf(v, __shfl_xor_sync(0xffffffffu, v, o));
    if ((threadIdx.x & 31) == 0) sc[threadIdx.x >> 5] = v;
    __syncthreads();
    float r = sc[0];
    #pragma unroll
    for (int i = 1; i < 8; i++) r = fmaxf(r, sc[i]);
    __syncthreads();
    return r;
}
__device__ __forceinline__ float blkSum256(float v, float* sc) {
    #pragma unroll
    for (int o = 16; o > 0; o >>= 1) v += __shfl_xor_sync(0xffffffffu, v, o);
    if ((threadIdx.x & 31) == 0) sc[threadIdx.x >> 5] = v;
    __syncthreads();
    float r = sc[0];
    #pragma unroll
    for (int i = 1; i < 8; i++) r += sc[i];
    __syncthreads();
    return r;
}
// pack two floats to f16x2: first arg -> low half, second -> high half
__device__ __forceinline__ unsigned packhf(float lo, float hi) {
    unsigned r;
    asm("cvt.rn.f16x2.f32 %0, %1, %2;" : "=r"(r) : "f"(hi), "f"(lo));
    return r;
}
__device__ __forceinline__ float lof16(unsigned h) {
    __half2 v = *reinterpret_cast<__half2*>(&h);
    return __low2float(v);
}
__device__ __forceinline__ float hif16(unsigned h) {
    __half2 v = *reinterpret_cast<__half2*>(&h);
    return __high2float(v);
}

__device__ __forceinline__ void cp16(void* dst, const void* src) {
    unsigned s = (unsigned)__cvta_generic_to_shared(dst);
    asm volatile("cp.async.cg.shared.global [%0], [%1], 16;\n" :: "r"(s), "l"(src));
}
__device__ __forceinline__ void cpcommit() { asm volatile("cp.async.commit_group;\n"); }
template <int N>
__device__ __forceinline__ void cpwait() { asm volatile("cp.async.wait_group %0;\n" :: "n"(N)); }

#define MMA_F16(c, a0, a1, a2, a3, b0, b1)                                             \
    asm volatile(                                                                       \
        "mma.sync.aligned.m16n8k16.row.col.f32.f16.f16.f32 "                            \
        "{%0,%1,%2,%3},{%4,%5,%6,%7},{%8,%9},{%0,%1,%2,%3};"                            \
        : "+f"((c)[0]), "+f"((c)[1]), "+f"((c)[2]), "+f"((c)[3])                        \
        : "r"(a0), "r"(a1), "r"(a2), "r"(a3), "r"(b0), "r"(b1))

// ---------------- P0: scalars ----------------
__global__ void k_scalars(const float* __restrict__ lT, const float* __restrict__ lc,
                          const void* __restrict__ tp) {
    if (threadIdx.x == 0) {
        unsigned w = *(const unsigned*)tp;
        float ft = __uint_as_float(w);
        float tempv = (fabsf(ft) > 1e-30f && fabsf(ft) < 1e30f) ? ft : (float)(int)w;
        float T = fminf(fmaxf(expf(lT[0]) * tempv, 0.05f), 10.0f);
        g_sc[0] = 1.0f / T;
        g_sc[1] = fminf(fmaxf(expf(lc[0]), 0.01f), 10.0f);
    }
}

// ---------------- P1: symmetric softmax -> At fp32 + f16x2 packed ----------------
__global__ void __launch_bounds__(256) k_adiff(const float* __restrict__ A) {
    __shared__ float scr[8];
    __shared__ float col[KCAP];
    const int j = blockIdx.x, tid = threadIdx.x;
    float v0 = 0.5f * (A[j * KCAP + tid]       + A[tid * KCAP + j]);
    float v1 = 0.5f * (A[j * KCAP + tid + 256] + A[(tid + 256) * KCAP + j]);
    float M = blkMax256(fmaxf(v0, v1), scr);
    float e0 = __expf(v0 - M), e1 = __expf(v1 - M);
    float S = blkSum256(e0 + e1, scr);
    float r = 0.1f / S;
    float a0 = e0 * r, a1 = e1 * r;
    g_At[tid * KCAP + j]         = a0;
    g_At[(tid + 256) * KCAP + j] = a1;
    col[tid] = a0; col[tid + 256] = a1;
    __syncthreads();
    // pack k-pairs: g_AtH[kpair*512 + n]
    g_AtH[tid * KCAP + j] = packhf(col[2 * tid], col[2 * tid + 1]);
}

// ---------------- P2: fold iteration 0 ----------------
__global__ void __launch_bounds__(256) k_prep(const float* __restrict__ brun) {
    __shared__ float br[KCAP];
    __shared__ float sg[KCAP];
    __shared__ float scr[8];
    const int tid = threadIdx.x;
    const float invT = g_sc[0];
    float v0 = brun[tid], v1 = brun[tid + 256];
    br[tid] = v0; br[tid + 256] = v1;
    float M = blkMax256(fmaxf(v0, v1), scr);
    float e0 = __expf((v0 - M) * invT), e1 = __expf((v1 - M) * invT);
    float S = blkSum256(e0 + e1, scr);
    float is = 1.0f / S;
    sg[tid] = e0 * is; sg[tid + 256] = e1 * is;
    __syncthreads();
    const int j = blockIdx.x * 256 + tid;
    float u = 0.0f, w = 0.0f;
    #pragma unroll 8
    for (int k = 0; k < KCAP; k++) {
        float at = g_At[k * KCAP + j];
        u = fmaf(br[k], at, u);
        w = fmaf(sg[k], at, w);
    }
    g_u1[j] = br[j] + u;
    g_w1[j] = sg[j] + w;
}

// ---------------- P3: fused x@W.T + row sum-of-squares via fp16 2-mma split ----------------
// u = (xh + xl) @ fp16(W); dropped term x @ (W - fp16(W)) ~ 2^-11 relative.
#define SSTRIDE 20
__global__ void __launch_bounds__(256) k_norm(const float* __restrict__ x,
                                              const float* __restrict__ W, int B) {
    __shared__ unsigned XH[128 * SSTRIDE];
    __shared__ unsigned XL[128 * SSTRIDE];
    __shared__ unsigned WH[128 * SSTRIDE];
    __shared__ float red2[128 * 2];

    const int tid  = threadIdx.x;
    const int lane = tid & 31;
    const int w    = tid >> 5;
    const int mrow = (w & 3) * 32;
    const int ncol = (w >> 2) * 64;
    const int row0 = blockIdx.x * 128;
    const int col0 = blockIdx.y * 128;

    const int srow = tid >> 1;
    const int soff = (tid & 1) * 16;
    const float* xp = x + (size_t)(row0 + srow) * DDIM + soff;
    const float* wp = W + (size_t)(col0 + srow) * DDIM + soff;
    const int sbase = srow * SSTRIDE + (tid & 1) * 8;

    float acc[2][8][4];
    #pragma unroll
    for (int mt = 0; mt < 2; mt++)
        #pragma unroll
        for (int nt = 0; nt < 8; nt++)
            #pragma unroll
            for (int q = 0; q < 4; q++) acc[mt][nt][q] = 0.0f;

    float4 rx[4], rw[4];
    #pragma unroll
    for (int i = 0; i < 4; i++) { rx[i] = *(const float4*)(xp + i * 4); rw[i] = *(const float4*)(wp + i * 4); }

    for (int kt = 0; kt < DDIM / 32; kt++) {
        __syncthreads();
        #pragma unroll
        for (int i = 0; i < 4; i++) {
            float4 v = rx[i];
            unsigned h0 = packhf(v.x, v.y);
            float l0 = v.x - lof16(h0);
            float l1 = v.y - hif16(h0);
            unsigned h1 = packhf(v.z, v.w);
            float l2 = v.z - lof16(h1);
            float l3 = v.w - hif16(h1);
            XH[sbase + i * 2]     = h0;
            XH[sbase + i * 2 + 1] = h1;
            XL[sbase + i * 2]     = packhf(l0, l1);
            XL[sbase + i * 2 + 1] = packhf(l2, l3);
            float4 u = rw[i];
            WH[sbase + i * 2]     = packhf(u.x, u.y);
            WH[sbase + i * 2 + 1] = packhf(u.z, u.w);
        }
        __syncthreads();
        if (kt < DDIM / 32 - 1) {
            const float* xq = xp + (kt + 1) * 32;
            const float* wq = wp + (kt + 1) * 32;
            #pragma unroll
            for (int i = 0; i < 4; i++) { rx[i] = *(const float4*)(xq + i * 4); rw[i] = *(const float4*)(wq + i * 4); }
        }
        #pragma unroll
        for (int c = 0; c < 2; c++) {
            const int kb = c * 8 + (lane & 3);
            unsigned ah[2][4], al[2][4];
            #pragma unroll
            for (int mt = 0; mt < 2; mt++) {
                int ra = (mrow + mt * 16 + (lane >> 2)) * SSTRIDE;
                ah[mt][0] = XH[ra + kb];
                ah[mt][1] = XH[ra + 8 * SSTRIDE + kb];
                ah[mt][2] = XH[ra + kb + 4];
                ah[mt][3] = XH[ra + 8 * SSTRIDE + kb + 4];
                al[mt][0] = XL[ra + kb];
                al[mt][1] = XL[ra + 8 * SSTRIDE + kb];
                al[mt][2] = XL[ra + kb + 4];
                al[mt][3] = XL[ra + 8 * SSTRIDE + kb + 4];
            }
            #pragma unroll
            for (int nt = 0; nt < 8; nt++) {
                int rb = (ncol + nt * 8 + (lane >> 2)) * SSTRIDE;
                unsigned bh0 = WH[rb + kb], bh1 = WH[rb + kb + 4];
                #pragma unroll
                for (int mt = 0; mt < 2; mt++) {
                    MMA_F16(acc[mt][nt], ah[mt][0], ah[mt][1], ah[mt][2], ah[mt][3], bh0, bh1);
                    MMA_F16(acc[mt][nt], al[mt][0], al[mt][1], al[mt][2], al[mt][3], bh0, bh1);
                }
            }
        }
    }

    #pragma unroll
    for (int mt = 0; mt < 2; mt++) {
        #pragma unroll
        for (int h = 0; h < 2; h++) {
            float s = 0.0f;
            #pragma unroll
            for (int nt = 0; nt < 8; nt++) {
                float a = acc[mt][nt][2 * h], b = acc[mt][nt][2 * h + 1];
                s = fmaf(a, a, fmaf(b, b, s));
            }
            s += __shfl_xor_sync(0xffffffffu, s, 1);
            s += __shfl_xor_sync(0xffffffffu, s, 2);
            if ((lane & 3) == 0) {
                int rloc = mrow + mt * 16 + (lane >> 2) + h * 8;
                red2[rloc * 2 + (w >> 2)] = s;
            }
        }
    }
    __syncthreads();
    if (tid < 128) {
        float s = red2[tid * 2] + red2[tid * 2 + 1];
        g_nsp[(size_t)blockIdx.y * B + row0 + tid] = s;
    }
}

// ---------------- P4: agreement ----------------
__global__ void k_agree(int B) {
    int i = blockIdx.x * 256 + threadIdx.x;
    if (i < B) {
        float c = g_sc[1];
        float ns = g_nsp[i] + g_nsp[B + i] + g_nsp[2 * B + i] + g_nsp[3 * B + i];
        ns = fmaxf(ns, 1e-10f);
        float sc2 = c * ns / (1.0f + c * ns);
        g_agr[i] = sc2 * sqrtf(ns);
    }
}

// ---------------- MAIN: 4 routing iterations, fp16 2-mma diffusion GEMM ----------------
// d = (bh + bl) @ fp16(At). Slab = k32 chunk of AtH, double-buffered (16 outer iters).
// smem: b_s[64*PAD] f32 | slabH 2x[16][PADU] u32 | red[512] | agrs[64]
#define SMEM_MAIN_FLOATS (64 * PAD + 2 * 16 * PADU + 512 + 64)
#define SMEM_MAIN_BYTES  (SMEM_MAIN_FLOATS * 4)

__global__ void __launch_bounds__(512, 1) k_main(float* __restrict__ out) {
    extern __shared__ float sm[];
    float*    b_s   = sm;                                  // [64][PAD]
    unsigned* slabH = (unsigned*)(sm + 64 * PAD);          // 2 x [16][PADU]
    float*    red   = (float*)(slabH + 2 * 16 * PADU);     // [512]
    float*    agrs  = red + 512;                           // [64]

    const int tid  = threadIdx.x;
    const int lane = tid & 31;
    const int wrp  = tid >> 5;               // 0..15
    const int rbase = (wrp & 3) * 16;        // row stripe
    const int nbase = (wrp >> 2) * 128;      // col stripe
    const int row0 = blockIdx.x * 64;
    const float invT = g_sc[0];

    const int r  = tid >> 3;                 // 0..63
    const int t8 = tid & 7;
    float* base = b_s + r * PAD + t8 * 4;

    if (tid < 64) agrs[tid] = g_agr[row0 + tid];
    float uj = g_u1[tid];
    float wj = g_w1[tid];
    __syncthreads();
    #pragma unroll 8
    for (int r2 = 0; r2 < 64; r2++)
        b_s[r2 * PAD + tid] = fmaf(agrs[r2], wj, uj);
    __syncthreads();

    for (int it = 0; it < 4; it++) {
        // prefetch k32 chunk 0 — overlaps with softmax
        {
            #pragma unroll
            for (int q = 0; q < 4; q++) {
                int lin = tid + q * 512;
                int rowk = lin >> 7, c4 = (lin & 127) * 4;
                cp16(slabH + rowk * PADU + c4, g_AtH + rowk * KCAP + c4);
            }
            cpcommit();
        }

        // ---- b += a * softmax(b/T) ----
        float mx = -3.4e38f;
        #pragma unroll
        for (int j = 0; j < 16; j++) {
            float4 v = *(const float4*)(base + j * 32);
            mx = fmaxf(mx, fmaxf(fmaxf(v.x, v.y), fmaxf(v.z, v.w)));
        }
        red[tid] = mx; __syncthreads();
        float m = red[r * 8];
        #pragma unroll
        for (int q = 1; q < 8; q++) m = fmaxf(m, red[r * 8 + q]);
        __syncthreads();
        float s = 0.0f;
        #pragma unroll
        for (int j = 0; j < 16; j++) {
            float4 v = *(const float4*)(base + j * 32);
            s += __expf((v.x - m) * invT) + __expf((v.y - m) * invT)
               + __expf((v.z - m) * invT) + __expf((v.w - m) * invT);
        }
        red[tid] = s; __syncthreads();
        float S = red[r * 8];
        #pragma unroll
        for (int q = 1; q < 8; q++) S += red[r * 8 + q];
        float aS = agrs[r] / S;
        #pragma unroll
        for (int j = 0; j < 16; j++) {
            float4 v = *(const float4*)(base + j * 32);
            v.x = fmaf(aS, __expf((v.x - m) * invT), v.x);
            v.y = fmaf(aS, __expf((v.y - m) * invT), v.y);
            v.z = fmaf(aS, __expf((v.z - m) * invT), v.z);
            v.w = fmaf(aS, __expf((v.w - m) * invT), v.w);
            *(float4*)(base + j * 32) = v;
        }
        __syncthreads();

        // ---- d = b @ AtH via fp16 2-mma split ----
        float acc[16][4];
        #pragma unroll
        for (int t = 0; t < 16; t++)
            #pragma unroll
            for (int q = 0; q < 4; q++) acc[t][q] = 0.0f;

        for (int kc = 0; kc < 16; kc++) {
            if (kc < 15) {
                int buf = (kc + 1) & 1;
                const unsigned* srcH = g_AtH + (kc + 1) * 16 * KCAP;
                unsigned* dstH = slabH + buf * 16 * PADU;
                #pragma unroll
                for (int q = 0; q < 4; q++) {
                    int lin = tid + q * 512;
                    int rowk = lin >> 7, c4 = (lin & 127) * 4;
                    cp16(dstH + rowk * PADU + c4, srcH + rowk * KCAP + c4);
                }
                cpcommit();
                cpwait<1>();
            } else {
                cpwait<0>();
            }
            __syncthreads();

            const unsigned* sH = slabH + (kc & 1) * 16 * PADU;

            #pragma unroll
            for (int g = 0; g < 2; g++) {
                const int k0 = kc * 32 + g * 16;
                // A fragments: rows rbase+(lane>>2), +8; k pairs (lane&3)*2, +8
                const float* ap = b_s + (rbase + (lane >> 2)) * PAD + k0 + (lane & 3) * 2;
                float2 v00 = *(const float2*)ap;
                float2 v10 = *(const float2*)(ap + 8 * PAD);
                float2 v01 = *(const float2*)(ap + 8);
                float2 v11 = *(const float2*)(ap + 8 * PAD + 8);
                unsigned ah0 = packhf(v00.x, v00.y);
                unsigned ah1 = packhf(v10.x, v10.y);
                unsigned ah2 = packhf(v01.x, v01.y);
                unsigned ah3 = packhf(v11.x, v11.y);
                unsigned al0 = packhf(v00.x - lof16(ah0), v00.y - hif16(ah0));
                unsigned al1 = packhf(v10.x - lof16(ah1), v10.y - hif16(ah1));
                unsigned al2 = packhf(v01.x - lof16(ah2), v01.y - hif16(ah2));
                unsigned al3 = packhf(v11.x - lof16(ah3), v11.y - hif16(ah3));

                const unsigned* bpH0 = sH + (g * 8 + (lane & 3)) * PADU + nbase + (lane >> 2);
                const unsigned* bpH1 = bpH0 + 4 * PADU;
                #pragma unroll
                for (int t = 0; t < 16; t++) {
                    unsigned bh0 = bpH0[t * 8], bh1 = bpH1[t * 8];
                    MMA_F16(acc[t], ah0, ah1, ah2, ah3, bh0, bh1);
                    MMA_F16(acc[t], al0, al1, al2, al3, bh0, bh1);
                }
            }
            __syncthreads();
        }

        // ---- b += d ----
        float* ep = b_s + (rbase + (lane >> 2)) * PAD + nbase + 2 * (lane & 3);
        #pragma unroll
        for (int t = 0; t < 16; t++) {
            float* p = ep + t * 8;
            p[0]           += acc[t][0];
            p[1]           += acc[t][1];
            p[8 * PAD]     += acc[t][2];
            p[8 * PAD + 1] += acc[t][3];
        }
        __syncthreads();
    }

    // ---- theta = softmax(b/T) -> out ----
    {
        float mx = -3.4e38f;
        #pragma unroll
        for (int j = 0; j < 16; j++) {
            float4 v = *(const float4*)(base + j * 32);
            mx = fmaxf(mx, fmaxf(fmaxf(v.x, v.y), fmaxf(v.z, v.w)));
        }
        red[tid] = mx; __syncthreads();
        float m = red[r * 8];
        #pragma unroll
        for (int q = 1; q < 8; q++) m = fmaxf(m, red[r * 8 + q]);
        __syncthreads();
        float s = 0.0f;
        #pragma unroll
        for (int j = 0; j < 16; j++) {
            float4 v = *(const float4*)(base + j * 32);
            s += __expf((v.x - m) * invT) + __expf((v.y - m) * invT)
               + __expf((v.z - m) * invT) + __expf((v.w - m) * invT);
        }
        red[tid] = s; __syncthreads();
        float S = red[r * 8];
        #pragma unroll
        for (int q = 1; q < 8; q++) S += red[r * 8 + q];
        float iS = 1.0f / S;
        float* op = out + (size_t)(row0 + r) * KCAP + t8 * 4;
        #pragma unroll
        for (int j = 0; j < 16; j++) {
            float4 v = *(const float4*)(base + j * 32);
            float4 o;
            o.x = __expf((v.x - m) * invT) * iS;
            o.y = __expf((v.y - m) * invT) * iS;
            o.z = __expf((v.z - m) * invT) * iS;
            o.w = __expf((v.w - m) * invT) * iS;
            *(float4*)(op + j * 32) = o;
        }
    }
}

// ---------------- launcher ----------------
extern "C" void kernel_launch(void* const* d_in, const int* in_sizes, int n_in,
                              void* d_out, int out_size) {
    const float* x    = (const float*)d_in[0];
    const float* W    = (const float*)d_in[1];
    const float* A    = (const float*)d_in[2];
    const float* lT   = (const float*)d_in[3];
    const float* lc   = (const float*)d_in[4];
    const float* brun = (const float*)d_in[5];
    const void*  temp = d_in[6];
    const int B = in_sizes[0] / DDIM;   // 16384

    cudaFuncSetAttribute(k_main, cudaFuncAttributeMaxDynamicSharedMemorySize,
                         SMEM_MAIN_BYTES);

    k_scalars<<<1, 32>>>(lT, lc, temp);
    k_adiff<<<KCAP, 256>>>(A);
    k_prep<<<2, 256>>>(brun);
    k_norm<<<dim3(B / 128, 4), 256>>>(x, W, B);
    k_agree<<<(B + 255) / 256, 256>>>(B);
    k_main<<<B / 64, 512, SMEM_MAIN_BYTES>>>((float*)d_out);
}

// round 7
// speedup vs baseline: 3.2123x; 1.0215x over previous
#include <cuda_runtime.h>
#include <cuda_fp16.h>
#include <cstdint>

#define KCAP 512
#define DDIM 1024
#define BMAX 16384
#define PAD  520

// ---------------- device scratch (no allocations allowed) ----------------
__device__ __align__(16) float g_At[KCAP * KCAP];   // fp32 0.1*A_diff^T (for k_prep)
// Permuted f16x2 At for k_main: [g(32)][bi(32)][n''(64)] uint2 {kpair g*8+kq, +4}
// bi = q*4 + kq, n = q + 8*n''  (q = n&7, n'' = n>>3)
__device__ __align__(16) uint2 g_AtP[32 * 32 * 64];
__device__ float g_nsp[4 * BMAX];
__device__ float g_agr[BMAX];
__device__ __align__(16) float g_u1[KCAP];
__device__ __align__(16) float g_w1[KCAP];
__device__ float g_sc[2];                            // {1/T_eff, c}

// ---------------- helpers ----------------
__device__ __forceinline__ float blkMax256(float v, float* sc) {
    #pragma unroll
    for (int o = 16; o > 0; o >>= 1) v = fmaxf(v, __shfl_xor_sync(0xffffffffu, v, o));
    if ((threadIdx.x & 31) == 0) sc[threadIdx.x >> 5] = v;
    __syncthreads();
    float r = sc[0];
    #pragma unroll
    for (int i = 1; i < 8; i++) r = fmaxf(r, sc[i]);
    __syncthreads();
    return r;
}
__device__ __forceinline__ float blkSum256(float v, float* sc) {
    #pragma unroll
    for (int o = 16; o > 0; o >>= 1) v += __shfl_xor_sync(0xffffffffu, v, o);
    if ((threadIdx.x & 31) == 0) sc[threadIdx.x >> 5] = v;
    __syncthreads();
    float r = sc[0];
    #pragma unroll
    for (int i = 1; i < 8; i++) r += sc[i];
    __syncthreads();
    return r;
}
// pack two floats to f16x2: first arg -> low half, second -> high half
__device__ __forceinline__ unsigned packhf(float lo, float hi) {
    unsigned r;
    asm("cvt.rn.f16x2.f32 %0, %1, %2;" : "=r"(r) : "f"(hi), "f"(lo));
    return r;
}
__device__ __forceinline__ float lof16(unsigned h) {
    __half2 v = *reinterpret_cast<__half2*>(&h);
    return __low2float(v);
}
__device__ __forceinline__ float hif16(unsigned h) {
    __half2 v = *reinterpret_cast<__half2*>(&h);
    return __high2float(v);
}

__device__ __forceinline__ void cp16(void* dst, const void* src) {
    unsigned s = (unsigned)__cvta_generic_to_shared(dst);
    asm volatile("cp.async.cg.shared.global [%0], [%1], 16;\n" :: "r"(s), "l"(src));
}
__device__ __forceinline__ void cpcommit() { asm volatile("cp.async.commit_group;\n"); }
template <int N>
__device__ __forceinline__ void cpwait() { asm volatile("cp.async.wait_group %0;\n" :: "n"(N)); }

#define MMA_F16(c, a0, a1, a2, a3, b0, b1)                                             \
    asm volatile(                                                                       \
        "mma.sync.aligned.m16n8k16.row.col.f32.f16.f16.f32 "                            \
        "{%0,%1,%2,%3},{%4,%5,%6,%7},{%8,%9},{%0,%1,%2,%3};"                            \
        : "+f"((c)[0]), "+f"((c)[1]), "+f"((c)[2]), "+f"((c)[3])                        \
        : "r"(a0), "r"(a1), "r"(a2), "r"(a3), "r"(b0), "r"(b1))

// ---------------- P0: scalars ----------------
__global__ void k_scalars(const float* __restrict__ lT, const float* __restrict__ lc,
                          const void* __restrict__ tp) {
    if (threadIdx.x == 0) {
        unsigned w = *(const unsigned*)tp;
        float ft = __uint_as_float(w);
        float tempv = (fabsf(ft) > 1e-30f && fabsf(ft) < 1e30f) ? ft : (float)(int)w;
        float T = fminf(fmaxf(expf(lT[0]) * tempv, 0.05f), 10.0f);
        g_sc[0] = 1.0f / T;
        g_sc[1] = fminf(fmaxf(expf(lc[0]), 0.01f), 10.0f);
    }
}

// ---------------- P1: symmetric softmax -> At fp32 + permuted f16x2 ----------------
__global__ void __launch_bounds__(256) k_adiff(const float* __restrict__ A) {
    __shared__ float scr[8];
    __shared__ float col[KCAP];
    const int j = blockIdx.x, tid = threadIdx.x;
    float v0 = 0.5f * (A[j * KCAP + tid]       + A[tid * KCAP + j]);
    float v1 = 0.5f * (A[j * KCAP + tid + 256] + A[(tid + 256) * KCAP + j]);
    float M = blkMax256(fmaxf(v0, v1), scr);
    float e0 = __expf(v0 - M), e1 = __expf(v1 - M);
    float S = blkSum256(e0 + e1, scr);
    float r = 0.1f / S;
    float a0 = e0 * r, a1 = e1 * r;
    g_At[tid * KCAP + j]         = a0;
    g_At[(tid + 256) * KCAP + j] = a1;
    col[tid] = a0; col[tid + 256] = a1;
    __syncthreads();
    // permuted layout: entries for n=j, all (g, kq)
    if (tid < 128) {
        int g = tid >> 2, kq = tid & 3;
        int p0 = g * 8 + kq;           // kpair for b0
        int p1 = p0 + 4;               // kpair for b1
        uint2 v;
        v.x = packhf(col[2 * p0], col[2 * p0 + 1]);
        v.y = packhf(col[2 * p1], col[2 * p1 + 1]);
        int q = j & 7, n2 = j >> 3;
        g_AtP[g * 2048 + (q * 4 + kq) * 64 + n2] = v;
    }
}

// ---------------- P2: fold iteration 0 ----------------
__global__ void __launch_bounds__(256) k_prep(const float* __restrict__ brun) {
    __shared__ float br[KCAP];
    __shared__ float sg[KCAP];
    __shared__ float scr[8];
    const int tid = threadIdx.x;
    const float invT = g_sc[0];
    float v0 = brun[tid], v1 = brun[tid + 256];
    br[tid] = v0; br[tid + 256] = v1;
    float M = blkMax256(fmaxf(v0, v1), scr);
    float e0 = __expf((v0 - M) * invT), e1 = __expf((v1 - M) * invT);
    float S = blkSum256(e0 + e1, scr);
    float is = 1.0f / S;
    sg[tid] = e0 * is; sg[tid + 256] = e1 * is;
    __syncthreads();
    const int j = blockIdx.x * 256 + tid;
    float u = 0.0f, w = 0.0f;
    #pragma unroll 8
    for (int k = 0; k < KCAP; k++) {
        float at = g_At[k * KCAP + j];
        u = fmaf(br[k], at, u);
        w = fmaf(sg[k], at, w);
    }
    g_u1[j] = br[j] + u;
    g_w1[j] = sg[j] + w;
}

// ---------------- P3: fused x@W.T + row sum-of-squares via fp16 2-mma split ----------------
#define SSTRIDE 20
__global__ void __launch_bounds__(256, 2) k_norm(const float* __restrict__ x,
                                                 const float* __restrict__ W, int B) {
    __shared__ unsigned XH[128 * SSTRIDE];
    __shared__ unsigned XL[128 * SSTRIDE];
    __shared__ unsigned WH[128 * SSTRIDE];
    __shared__ float red2[128 * 2];

    const int tid  = threadIdx.x;
    const int lane = tid & 31;
    const int w    = tid >> 5;
    const int mrow = (w & 3) * 32;
    const int ncol = (w >> 2) * 64;
    const int row0 = blockIdx.x * 128;
    const int col0 = blockIdx.y * 128;

    const int srow = tid >> 1;
    const int soff = (tid & 1) * 16;
    const float* xp = x + (size_t)(row0 + srow) * DDIM + soff;
    const float* wp = W + (size_t)(col0 + srow) * DDIM + soff;
    const int sbase = srow * SSTRIDE + (tid & 1) * 8;

    float acc[2][8][4];
    #pragma unroll
    for (int mt = 0; mt < 2; mt++)
        #pragma unroll
        for (int nt = 0; nt < 8; nt++)
            #pragma unroll
            for (int q = 0; q < 4; q++) acc[mt][nt][q] = 0.0f;

    float4 rx[4], rw[4];
    #pragma unroll
    for (int i = 0; i < 4; i++) { rx[i] = *(const float4*)(xp + i * 4); rw[i] = *(const float4*)(wp + i * 4); }

    for (int kt = 0; kt < DDIM / 32; kt++) {
        __syncthreads();
        #pragma unroll
        for (int i = 0; i < 4; i++) {
            float4 v = rx[i];
            unsigned h0 = packhf(v.x, v.y);
            float l0 = v.x - lof16(h0);
            float l1 = v.y - hif16(h0);
            unsigned h1 = packhf(v.z, v.w);
            float l2 = v.z - lof16(h1);
            float l3 = v.w - hif16(h1);
            XH[sbase + i * 2]     = h0;
            XH[sbase + i * 2 + 1] = h1;
            XL[sbase + i * 2]     = packhf(l0, l1);
            XL[sbase + i * 2 + 1] = packhf(l2, l3);
            float4 u = rw[i];
            WH[sbase + i * 2]     = packhf(u.x, u.y);
            WH[sbase + i * 2 + 1] = packhf(u.z, u.w);
        }
        __syncthreads();
        if (kt < DDIM / 32 - 1) {
            const float* xq = xp + (kt + 1) * 32;
            const float* wq = wp + (kt + 1) * 32;
            #pragma unroll
            for (int i = 0; i < 4; i++) { rx[i] = *(const float4*)(xq + i * 4); rw[i] = *(const float4*)(wq + i * 4); }
        }
        #pragma unroll
        for (int c = 0; c < 2; c++) {
            const int kb = c * 8 + (lane & 3);
            unsigned ah[2][4], al[2][4];
            #pragma unroll
            for (int mt = 0; mt < 2; mt++) {
                int ra = (mrow + mt * 16 + (lane >> 2)) * SSTRIDE;
                ah[mt][0] = XH[ra + kb];
                ah[mt][1] = XH[ra + 8 * SSTRIDE + kb];
                ah[mt][2] = XH[ra + kb + 4];
                ah[mt][3] = XH[ra + 8 * SSTRIDE + kb + 4];
                al[mt][0] = XL[ra + kb];
                al[mt][1] = XL[ra + 8 * SSTRIDE + kb];
                al[mt][2] = XL[ra + kb + 4];
                al[mt][3] = XL[ra + 8 * SSTRIDE + kb + 4];
            }
            #pragma unroll
            for (int nt = 0; nt < 8; nt++) {
                int rb = (ncol + nt * 8 + (lane >> 2)) * SSTRIDE;
                unsigned bh0 = WH[rb + kb], bh1 = WH[rb + kb + 4];
                #pragma unroll
                for (int mt = 0; mt < 2; mt++) {
                    MMA_F16(acc[mt][nt], ah[mt][0], ah[mt][1], ah[mt][2], ah[mt][3], bh0, bh1);
                    MMA_F16(acc[mt][nt], al[mt][0], al[mt][1], al[mt][2], al[mt][3], bh0, bh1);
                }
            }
        }
    }

    #pragma unroll
    for (int mt = 0; mt < 2; mt++) {
        #pragma unroll
        for (int h = 0; h < 2; h++) {
            float s = 0.0f;
            #pragma unroll
            for (int nt = 0; nt < 8; nt++) {
                float a = acc[mt][nt][2 * h], b = acc[mt][nt][2 * h + 1];
                s = fmaf(a, a, fmaf(b, b, s));
            }
            s += __shfl_xor_sync(0xffffffffu, s, 1);
            s += __shfl_xor_sync(0xffffffffu, s, 2);
            if ((lane & 3) == 0) {
                int rloc = mrow + mt * 16 + (lane >> 2) + h * 8;
                red2[rloc * 2 + (w >> 2)] = s;
            }
        }
    }
    __syncthreads();
    if (tid < 128) {
        float s = red2[tid * 2] + red2[tid * 2 + 1];
        g_nsp[(size_t)blockIdx.y * B + row0 + tid] = s;
    }
}

// ---------------- P4: agreement ----------------
__global__ void k_agree(int B) {
    int i = blockIdx.x * 256 + threadIdx.x;
    if (i < B) {
        float c = g_sc[1];
        float ns = g_nsp[i] + g_nsp[B + i] + g_nsp[2 * B + i] + g_nsp[3 * B + i];
        ns = fmaxf(ns, 1e-10f);
        float sc2 = c * ns / (1.0f + c * ns);
        g_agr[i] = sc2 * sqrtf(ns);
    }
}

// ---------------- MAIN: 4 routing iterations, fp16 2-mma diffusion GEMM ----------------
// Slab per kc: 2 g-groups x 32 blocks x 66 uint2 (64 data + 2 pad) = 4224 uint2.
// Block stride 132 words -> 8-lane phases hit distinct 16B banks for LDS.128.
#define GSLAB 2112                 // uint2 per g-group in smem (32 * 66)
#define SLABU (2 * GSLAB)          // uint2 per kc buffer
#define SMEM_MAIN_BYTES (64 * PAD * 4 + 2 * SLABU * 8 + 512 * 4 + 64 * 4)

__global__ void __launch_bounds__(512, 1) k_main(float* __restrict__ out) {
    extern __shared__ float sm[];
    float* b_s   = sm;                                  // [64][PAD]
    uint2* slab  = (uint2*)(sm + 64 * PAD);             // 2 x SLABU
    float* red   = (float*)(slab + 2 * SLABU);          // [512]
    float* agrs  = red + 512;                           // [64]

    const int tid  = threadIdx.x;
    const int lane = tid & 31;
    const int wrp  = tid >> 5;               // 0..15
    const int rbase = (wrp & 3) * 16;        // row stripe
    const int nbase = (wrp >> 2) * 128;      // col stripe
    const int n2b   = (wrp >> 2) * 16;       // n'' base
    const int row0 = blockIdx.x * 64;
    const float invT = g_sc[0];

    const int r  = tid >> 3;                 // 0..63
    const int t8 = tid & 7;
    float* base = b_s + r * PAD + t8 * 4;

    // cp.async mapping: 2048 16B-chunks per kc, 4 per thread
    // chunk c: g' = c>>10, bi = (c>>5)&31, off = (c&31)*2 (uint2)
    if (tid < 64) agrs[tid] = g_agr[row0 + tid];
    float uj = g_u1[tid];
    float wj = g_w1[tid];
    __syncthreads();
    #pragma unroll 8
    for (int r2 = 0; r2 < 64; r2++)
        b_s[r2 * PAD + tid] = fmaf(agrs[r2], wj, uj);
    __syncthreads();

    for (int it = 0; it < 4; it++) {
        // prefetch kc=0 slab — overlaps with softmax
        {
            #pragma unroll
            for (int q = 0; q < 4; q++) {
                int c = tid + q * 512;
                int gg = c >> 10, bi = (c >> 5) & 31, off = (c & 31) * 2;
                cp16(slab + gg * GSLAB + bi * 66 + off,
                     g_AtP + gg * 2048 + bi * 64 + off);
            }
            cpcommit();
        }

        // ---- b += a * softmax(b/T) ----
        float mx = -3.4e38f;
        #pragma unroll
        for (int j = 0; j < 16; j++) {
            float4 v = *(const float4*)(base + j * 32);
            mx = fmaxf(mx, fmaxf(fmaxf(v.x, v.y), fmaxf(v.z, v.w)));
        }
        red[tid] = mx; __syncthreads();
        float m = red[r * 8];
        #pragma unroll
        for (int q = 1; q < 8; q++) m = fmaxf(m, red[r * 8 + q]);
        __syncthreads();
        float s = 0.0f;
        #pragma unroll
        for (int j = 0; j < 16; j++) {
            float4 v = *(const float4*)(base + j * 32);
            s += __expf((v.x - m) * invT) + __expf((v.y - m) * invT)
               + __expf((v.z - m) * invT) + __expf((v.w - m) * invT);
        }
        red[tid] = s; __syncthreads();
        float S = red[r * 8];
        #pragma unroll
        for (int q = 1; q < 8; q++) S += red[r * 8 + q];
        float aS = agrs[r] / S;
        #pragma unroll
        for (int j = 0; j < 16; j++) {
            float4 v = *(const float4*)(base + j * 32);
            v.x = fmaf(aS, __expf((v.x - m) * invT), v.x);
            v.y = fmaf(aS, __expf((v.y - m) * invT), v.y);
            v.z = fmaf(aS, __expf((v.z - m) * invT), v.z);
            v.w = fmaf(aS, __expf((v.w - m) * invT), v.w);
            *(float4*)(base + j * 32) = v;
        }
        __syncthreads();

        // ---- d = b @ AtH via fp16 2-mma split, vectorized B loads ----
        float acc[16][4];
        #pragma unroll
        for (int t = 0; t < 16; t++)
            #pragma unroll
            for (int q = 0; q < 4; q++) acc[t][q] = 0.0f;

        for (int kc = 0; kc < 16; kc++) {
            if (kc < 15) {
                const uint2* src = g_AtP + (kc + 1) * 2 * 2048;
                uint2* dst = slab + ((kc + 1) & 1) * SLABU;
                #pragma unroll
                for (int q = 0; q < 4; q++) {
                    int c = tid + q * 512;
                    int gg = c >> 10, bi = (c >> 5) & 31, off = (c & 31) * 2;
                    cp16(dst + gg * GSLAB + bi * 66 + off,
                         src + gg * 2048 + bi * 64 + off);
                }
                cpcommit();
                cpwait<1>();
            } else {
                cpwait<0>();
            }
            __syncthreads();

            const uint2* sB = slab + (kc & 1) * SLABU;

            #pragma unroll
            for (int g = 0; g < 2; g++) {
                const int k0 = kc * 32 + g * 16;
                // A fragments: rows rbase+(lane>>2), +8; k pairs (lane&3)*2, +8
                const float* ap = b_s + (rbase + (lane >> 2)) * PAD + k0 + (lane & 3) * 2;
                float2 v00 = *(const float2*)ap;
                float2 v10 = *(const float2*)(ap + 8 * PAD);
                float2 v01 = *(const float2*)(ap + 8);
                float2 v11 = *(const float2*)(ap + 8 * PAD + 8);
                unsigned ah0 = packhf(v00.x, v00.y);
                unsigned ah1 = packhf(v10.x, v10.y);
                unsigned ah2 = packhf(v01.x, v01.y);
                unsigned ah3 = packhf(v11.x, v11.y);
                unsigned al0 = packhf(v00.x - lof16(ah0), v00.y - hif16(ah0));
                unsigned al1 = packhf(v10.x - lof16(ah1), v10.y - hif16(ah1));
                unsigned al2 = packhf(v01.x - lof16(ah2), v01.y - hif16(ah2));
                unsigned al3 = packhf(v11.x - lof16(ah3), v11.y - hif16(ah3));

                // B fragments: block bi = lane, 16 consecutive uint2 from n2b
                const uint4* bp = (const uint4*)(sB + g * GSLAB + lane * 66 + n2b);
                #pragma unroll
                for (int jj = 0; jj < 8; jj++) {
                    uint4 bv = bp[jj];   // {b0(t=2jj), b1(t=2jj), b0(t=2jj+1), b1(t=2jj+1)}
                    MMA_F16(acc[2 * jj],     ah0, ah1, ah2, ah3, bv.x, bv.y);
                    MMA_F16(acc[2 * jj],     al0, al1, al2, al3, bv.x, bv.y);
                    MMA_F16(acc[2 * jj + 1], ah0, ah1, ah2, ah3, bv.z, bv.w);
                    MMA_F16(acc[2 * jj + 1], al0, al1, al2, al3, bv.z, bv.w);
                }
            }
            __syncthreads();
        }

        // ---- b += d ----
        float* ep = b_s + (rbase + (lane >> 2)) * PAD + nbase + 2 * (lane & 3);
        #pragma unroll
        for (int t = 0; t < 16; t++) {
            float* p = ep + t * 8;
            p[0]           += acc[t][0];
            p[1]           += acc[t][1];
            p[8 * PAD]     += acc[t][2];
            p[8 * PAD + 1] += acc[t][3];
        }
        __syncthreads();
    }

    // ---- theta = softmax(b/T) -> out ----
    {
        float mx = -3.4e38f;
        #pragma unroll
        for (int j = 0; j < 16; j++) {
            float4 v = *(const float4*)(base + j * 32);
            mx = fmaxf(mx, fmaxf(fmaxf(v.x, v.y), fmaxf(v.z, v.w)));
        }
        red[tid] = mx; __syncthreads();
        float m = red[r * 8];
        #pragma unroll
        for (int q = 1; q < 8; q++) m = fmaxf(m, red[r * 8 + q]);
        __syncthreads();
        float s = 0.0f;
        #pragma unroll
        for (int j = 0; j < 16; j++) {
            float4 v = *(const float4*)(base + j * 32);
            s += __expf((v.x - m) * invT) + __expf((v.y - m) * invT)
               + __expf((v.z - m) * invT) + __expf((v.w - m) * invT);
        }
        red[tid] = s; __syncthreads();
        float S = red[r * 8];
        #pragma unroll
        for (int q = 1; q < 8; q++) S += red[r * 8 + q];
        float iS = 1.0f / S;
        float* op = out + (size_t)(row0 + r) * KCAP + t8 * 4;
        #pragma unroll
        for (int j = 0; j < 16; j++) {
            float4 v = *(const float4*)(base + j * 32);
            float4 o;
            o.x = __expf((v.x - m) * invT) * iS;
            o.y = __expf((v.y - m) * invT) * iS;
            o.z = __expf((v.z - m) * invT) * iS;
            o.w = __expf((v.w - m) * invT) * iS;
            *(float4*)(op + j * 32) = o;
        }
    }
}

// ---------------- launcher ----------------
extern "C" void kernel_launch(void* const* d_in, const int* in_sizes, int n_in,
                              void* d_out, int out_size) {
    const float* x    = (const float*)d_in[0];
    const float* W    = (const float*)d_in[1];
    const float* A    = (const float*)d_in[2];
    const float* lT   = (const float*)d_in[3];
    const float* lc   = (const float*)d_in[4];
    const float* brun = (const float*)d_in[5];
    const void*  temp = d_in[6];
    const int B = in_sizes[0] / DDIM;   // 16384

    cudaFuncSetAttribute(k_main, cudaFuncAttributeMaxDynamicSharedMemorySize,
                         SMEM_MAIN_BYTES);

    k_scalars<<<1, 32>>>(lT, lc, temp);
    k_adiff<<<KCAP, 256>>>(A);
    k_prep<<<2, 256>>>(brun);
    k_norm<<<dim3(B / 128, 4), 256>>>(x, W, B);
    k_agree<<<(B + 255) / 256, 256>>>(B);
    k_main<<<B / 64, 512, SMEM_MAIN_BYTES>>>((float*)d_out);
}